// round 6
// baseline (speedup 1.0000x reference)
#include <cuda_runtime.h>
#include <cuda_bf16.h>
#include <math.h>
#include <stdint.h>

// ---------------- problem constants ----------------
#define B_ 2
#define T_ 4096
#define HID_ 2048
#define H_ 6
#define DKH 256
#define DVH 512
#define KEYD 1536
#define VALD 3072
#define ROWS_ (B_ * T_)          // 8192
#define DVS 64                   // dv slice per scan CTA
#define NSL 8                    // 512/64
#define TOKB 8                   // tokens staged per scan round

// ---------------- scratch (device globals; no allocation allowed) ----------------
__device__ float g_xq[ROWS_ * KEYD];
__device__ float g_xk[ROWS_ * KEYD];
__device__ float g_xv[ROWS_ * VALD];
__device__ float g_gt[ROWS_ * VALD];
__device__ float g_qn[ROWS_ * KEYD];
__device__ float g_kn[ROWS_ * KEYD];
__device__ float g_vn[ROWS_ * VALD];
__device__ float g_od[ROWS_ * VALD];
__device__ float g_gd[ROWS_ * H_];
__device__ float g_bt[ROWS_ * H_];
__device__ float g_wat[H_ * HID_];
__device__ float g_wbt[H_ * HID_];
// bf16 split buffers
__device__ __nv_bfloat16 g_ahi[ROWS_ * HID_];
__device__ __nv_bfloat16 g_alo[ROWS_ * HID_];
__device__ __nv_bfloat16 g_yhi[ROWS_ * VALD];
__device__ __nv_bfloat16 g_ylo[ROWS_ * VALD];
__device__ __nv_bfloat16 g_wqh[KEYD * HID_];
__device__ __nv_bfloat16 g_wql[KEYD * HID_];
__device__ __nv_bfloat16 g_wkh[KEYD * HID_];
__device__ __nv_bfloat16 g_wkl[KEYD * HID_];
__device__ __nv_bfloat16 g_wvh[VALD * HID_];
__device__ __nv_bfloat16 g_wvl[VALD * HID_];
__device__ __nv_bfloat16 g_wgh[VALD * HID_];
__device__ __nv_bfloat16 g_wgl[VALD * HID_];
__device__ __nv_bfloat16 g_woh[HID_ * VALD];
__device__ __nv_bfloat16 g_wol[HID_ * VALD];

// ---------------- packed f32x2 helpers ----------------
__device__ __forceinline__ unsigned long long pk2(float x, float y) {
    unsigned long long r;
    asm("mov.b64 %0, {%1, %2};" : "=l"(r) : "f"(x), "f"(y));
    return r;
}
__device__ __forceinline__ float2 up2(unsigned long long v) {
    float2 r;
    asm("mov.b64 {%0, %1}, %2;" : "=f"(r.x), "=f"(r.y) : "l"(v));
    return r;
}
__device__ __forceinline__ unsigned long long fma2u(unsigned long long a, unsigned long long b, unsigned long long c) {
    unsigned long long d;
    asm("fma.rn.f32x2 %0, %1, %2, %3;" : "=l"(d) : "l"(a), "l"(b), "l"(c));
    return d;
}
__device__ __forceinline__ unsigned long long mul2u(unsigned long long a, unsigned long long b) {
    unsigned long long d;
    asm("mul.rn.f32x2 %0, %1, %2;" : "=l"(d) : "l"(a), "l"(b));
    return d;
}

// ---------------- mma.sync / ldmatrix / cp.async helpers (sm_80 ISA, works on sm_103 target) ----------------
__device__ __forceinline__ uint32_t smem_u32(const void* p) {
    uint32_t a;
    asm("{ .reg .u64 t; cvta.to.shared.u64 t, %1; cvt.u32.u64 %0, t; }" : "=r"(a) : "l"(p));
    return a;
}
__device__ __forceinline__ void ldm_x4(uint32_t* r, uint32_t addr) {
    asm volatile("ldmatrix.sync.aligned.m8n8.x4.shared.b16 {%0,%1,%2,%3}, [%4];"
                 : "=r"(r[0]), "=r"(r[1]), "=r"(r[2]), "=r"(r[3]) : "r"(addr));
}
__device__ __forceinline__ void ldm_x2(uint32_t* r, uint32_t addr) {
    asm volatile("ldmatrix.sync.aligned.m8n8.x2.shared.b16 {%0,%1}, [%2];"
                 : "=r"(r[0]), "=r"(r[1]) : "r"(addr));
}
__device__ __forceinline__ void mma16816(float* c, const uint32_t* a, const uint32_t* b) {
    asm volatile("mma.sync.aligned.m16n8k16.row.col.f32.bf16.bf16.f32 "
                 "{%0,%1,%2,%3}, {%4,%5,%6,%7}, {%8,%9}, {%0,%1,%2,%3};"
                 : "+f"(c[0]), "+f"(c[1]), "+f"(c[2]), "+f"(c[3])
                 : "r"(a[0]), "r"(a[1]), "r"(a[2]), "r"(a[3]), "r"(b[0]), "r"(b[1]));
}
__device__ __forceinline__ void cp16(uint32_t sm, const void* gp) {
    asm volatile("cp.async.cg.shared.global [%0], [%1], 16;" :: "r"(sm), "l"(gp));
}
#define CP_COMMIT() asm volatile("cp.async.commit_group;" ::: "memory")
#define CP_WAIT0()  asm volatile("cp.async.wait_group 0;" ::: "memory")

// ---------------- bf16-split HMMA GEMM ----------------
// C[M,N] = A[M,K] @ B^T; A row-major (hi/lo bf16), B stored [N,K] (hi/lo bf16).
// CTA 128x128, 256 threads, warp tile 64x32, K-chunk 64, cp.async double buffer.
// SMEM rows padded to 72 bf16 (144B) -> conflict-free ldmatrix.
#define GTILE 18432            // 128 rows * 144 B
#define GBUF  73728            // 4 tiles
#define GEMM_SMEM 147456       // 2 buffers

__global__ __launch_bounds__(256, 1)
void gemm_bf16x3(const __nv_bfloat16* __restrict__ Ahi, const __nv_bfloat16* __restrict__ Alo,
                 const __nv_bfloat16* __restrict__ Bhi, const __nv_bfloat16* __restrict__ Blo,
                 float* __restrict__ C, int M, int N, int K) {
    extern __shared__ __align__(16) char smem[];
    const uint32_t sbase = smem_u32(smem);
    const int tid = threadIdx.x, lane = tid & 31, wid = tid >> 5;
    const int wm = wid & 1, wn = wid >> 1;      // 2 x 4 warp grid
    const int brow = blockIdx.y * 128, bcol = blockIdx.x * 128;

    const __nv_bfloat16* srcs[4] = {Ahi, Alo, Bhi, Blo};
    const int row0[4] = {brow, brow, bcol, bcol};

    float acc[4][4][4];
#pragma unroll
    for (int i = 0; i < 4; i++)
#pragma unroll
        for (int j = 0; j < 4; j++)
#pragma unroll
            for (int l = 0; l < 4; l++) acc[i][j][l] = 0.f;

    const int r_ = tid >> 3, c8_ = (tid & 7) * 8;   // per-thread load coords (stride 32 rows / iter)

    // prologue: chunk 0 -> buf 0
#pragma unroll
    for (int ts = 0; ts < 4; ts++) {
        const __nv_bfloat16* sp = srcs[ts] + (size_t)(row0[ts] + r_) * K + c8_;
        uint32_t tb = sbase + ts * GTILE + r_ * 144 + c8_ * 2;
#pragma unroll
        for (int i = 0; i < 4; i++)
            cp16(tb + i * 32 * 144, sp + (size_t)(i * 32) * K);
    }
    CP_COMMIT();
    CP_WAIT0();
    __syncthreads();

    const int numT = K >> 6;
    const uint32_t a_lane = (lane & 15) * 144 + (lane >> 4) * 16;
    const uint32_t b_lane = (lane & 7) * 144 + ((lane >> 3) & 1) * 16;

    for (int c = 0; c < numT; c++) {
        const int b = c & 1;
        if (c + 1 < numT) {
            const int kc = (c + 1) << 6, nb = b ^ 1;
#pragma unroll
            for (int ts = 0; ts < 4; ts++) {
                const __nv_bfloat16* sp = srcs[ts] + (size_t)(row0[ts] + r_) * K + kc + c8_;
                uint32_t tb = sbase + nb * GBUF + ts * GTILE + r_ * 144 + c8_ * 2;
#pragma unroll
                for (int i = 0; i < 4; i++)
                    cp16(tb + i * 32 * 144, sp + (size_t)(i * 32) * K);
            }
            CP_COMMIT();
        }
        const uint32_t aH = sbase + b * GBUF + wm * 64 * 144;
        const uint32_t aL = aH + GTILE;
        const uint32_t bH = sbase + b * GBUF + 2 * GTILE + wn * 32 * 144;
        const uint32_t bL = bH + GTILE;
#pragma unroll
        for (int ks = 0; ks < 4; ks++) {
            const uint32_t acol = ks * 32 + a_lane;
            const uint32_t bcol2 = ks * 32 + b_lane;
            uint32_t fAH[4][4], fAL[4][4], fBH[4][2], fBL[4][2];
#pragma unroll
            for (int mt = 0; mt < 4; mt++) {
                ldm_x4(fAH[mt], aH + mt * 16 * 144 + acol);
                ldm_x4(fAL[mt], aL + mt * 16 * 144 + acol);
            }
#pragma unroll
            for (int nt = 0; nt < 4; nt++) {
                ldm_x2(fBH[nt], bH + nt * 8 * 144 + bcol2);
                ldm_x2(fBL[nt], bL + nt * 8 * 144 + bcol2);
            }
#pragma unroll
            for (int mt = 0; mt < 4; mt++)
#pragma unroll
                for (int nt = 0; nt < 4; nt++) {
                    mma16816(acc[mt][nt], fAH[mt], fBH[nt]);
                    mma16816(acc[mt][nt], fAL[mt], fBH[nt]);
                    mma16816(acc[mt][nt], fAH[mt], fBL[nt]);
                }
        }
        CP_WAIT0();
        __syncthreads();
    }

    // epilogue: fp32 C fragments straight to global
    const int r0 = lane >> 2, cc = (lane & 3) * 2;
#pragma unroll
    for (int mt = 0; mt < 4; mt++)
#pragma unroll
        for (int nt = 0; nt < 4; nt++) {
            size_t base = (size_t)(brow + wm * 64 + mt * 16 + r0) * N + bcol + wn * 32 + nt * 8 + cc;
            *(float2*)&C[base] = make_float2(acc[mt][nt][0], acc[mt][nt][1]);
            *(float2*)&C[base + 8 * (size_t)N] = make_float2(acc[mt][nt][2], acc[mt][nt][3]);
        }
}

// ---------------- fp32 -> bf16 hi/lo split (row-major, vectorized) ----------------
__global__ void split4(const float* __restrict__ x, __nv_bfloat16* __restrict__ xh,
                       __nv_bfloat16* __restrict__ xl) {
    int i4 = blockIdx.x * 256 + threadIdx.x;
    float4 v = ((const float4*)x)[i4];
    __nv_bfloat16 h0 = __float2bfloat16(v.x), h1 = __float2bfloat16(v.y);
    __nv_bfloat16 h2 = __float2bfloat16(v.z), h3 = __float2bfloat16(v.w);
    __nv_bfloat16 l0 = __float2bfloat16(v.x - __bfloat162float(h0));
    __nv_bfloat16 l1 = __float2bfloat16(v.y - __bfloat162float(h1));
    __nv_bfloat16 l2 = __float2bfloat16(v.z - __bfloat162float(h2));
    __nv_bfloat16 l3 = __float2bfloat16(v.w - __bfloat162float(h3));
    __nv_bfloat162* hp = (__nv_bfloat162*)(xh + (size_t)i4 * 4);
    __nv_bfloat162* lp = (__nv_bfloat162*)(xl + (size_t)i4 * 4);
    hp[0] = __nv_bfloat162(h0, h1); hp[1] = __nv_bfloat162(h2, h3);
    lp[0] = __nv_bfloat162(l0, l1); lp[1] = __nv_bfloat162(l2, l3);
}

// ---------------- weight transpose + split: W[K,N] -> Whi/Wlo [N,K] bf16 ----------------
__global__ void tsplit(const float* __restrict__ W, __nv_bfloat16* __restrict__ Wh,
                       __nv_bfloat16* __restrict__ Wl, int K, int N) {
    __shared__ float tile[32][33];
    int n0 = blockIdx.x * 32, k0 = blockIdx.y * 32;
    int tx = threadIdx.x & 31, ty = threadIdx.x >> 5;   // 32x8
#pragma unroll
    for (int i = 0; i < 4; i++) {
        int k = k0 + ty + i * 8;
        tile[ty + i * 8][tx] = W[(size_t)k * N + n0 + tx];
    }
    __syncthreads();
#pragma unroll
    for (int i = 0; i < 4; i++) {
        int n = n0 + ty + i * 8;
        float x = tile[tx][ty + i * 8];
        __nv_bfloat16 h = __float2bfloat16(x);
        Wh[(size_t)n * K + k0 + tx] = h;
        Wl[(size_t)n * K + k0 + tx] = __float2bfloat16(x - __bfloat162float(h));
    }
}

// ---------------- causal depthwise conv (K=4) + SiLU ----------------
__global__ void conv_silu_k(const float* __restrict__ x, const float* __restrict__ w,
                            float* __restrict__ y, int D) {
    int idx = blockIdx.x * 256 + threadIdx.x;
    int d = idx % D;
    int t = (idx / D) & (T_ - 1);
    float4 wv = *(const float4*)(w + d * 4);
    float acc = x[idx] * wv.w;
    if (t >= 1) acc += x[idx - D] * wv.z;
    if (t >= 2) acc += x[idx - 2 * D] * wv.y;
    if (t >= 3) acc += x[idx - 3 * D] * wv.x;
    y[idx] = acc / (1.f + expf(-acc));
}

// ---------------- per-(b,t,h) L2 norm over 256, in place, times scale ----------------
__global__ void l2norm_k(float* __restrict__ x, float scale) {
    int gw = (blockIdx.x * 256 + threadIdx.x) >> 5;
    int lane = threadIdx.x & 31;
    float* row = x + (size_t)gw * DKH;
    float4 v0 = *(const float4*)(row + lane * 8);
    float4 v1 = *(const float4*)(row + lane * 8 + 4);
    float ss = v0.x * v0.x + v0.y * v0.y + v0.z * v0.z + v0.w * v0.w +
               v1.x * v1.x + v1.y * v1.y + v1.z * v1.z + v1.w * v1.w;
#pragma unroll
    for (int o = 16; o; o >>= 1) ss += __shfl_xor_sync(0xffffffffu, ss, o);
    float r = rsqrtf(ss) * scale;
    v0.x *= r; v0.y *= r; v0.z *= r; v0.w *= r;
    v1.x *= r; v1.y *= r; v1.z *= r; v1.w *= r;
    *(float4*)(row + lane * 8) = v0;
    *(float4*)(row + lane * 8 + 4) = v1;
}

// ---------------- transpose Wa/Wb (2048x6 -> 6x2048) ----------------
__global__ void transpose6(const float* __restrict__ Wa, const float* __restrict__ Wb,
                           float* __restrict__ WaT, float* __restrict__ WbT) {
    int i = blockIdx.x * 256 + threadIdx.x;
    int c = i / H_, h = i % H_;
    WaT[h * HID_ + c] = Wa[i];
    WbT[h * HID_ + c] = Wb[i];
}

// ---------------- beta / decay projection ----------------
__global__ void proj_ab(const float* __restrict__ hid, const float* __restrict__ WaT,
                        const float* __restrict__ WbT, const float* __restrict__ A_log,
                        const float* __restrict__ dt_bias,
                        float* __restrict__ gdec, float* __restrict__ beta) {
    int gw = (blockIdx.x * 256 + threadIdx.x) >> 5;
    int lane = threadIdx.x & 31;
    const float* hr = hid + (size_t)gw * HID_;
    float da0 = 0, da1 = 0, da2 = 0, da3 = 0, da4 = 0, da5 = 0;
    float db0 = 0, db1 = 0, db2 = 0, db3 = 0, db4 = 0, db5 = 0;
    for (int c = lane; c < HID_; c += 32) {
        float hv = hr[c];
        da0 += hv * WaT[0 * HID_ + c]; db0 += hv * WbT[0 * HID_ + c];
        da1 += hv * WaT[1 * HID_ + c]; db1 += hv * WbT[1 * HID_ + c];
        da2 += hv * WaT[2 * HID_ + c]; db2 += hv * WbT[2 * HID_ + c];
        da3 += hv * WaT[3 * HID_ + c]; db3 += hv * WbT[3 * HID_ + c];
        da4 += hv * WaT[4 * HID_ + c]; db4 += hv * WbT[4 * HID_ + c];
        da5 += hv * WaT[5 * HID_ + c]; db5 += hv * WbT[5 * HID_ + c];
    }
#pragma unroll
    for (int o = 16; o; o >>= 1) {
        da0 += __shfl_xor_sync(~0u, da0, o); db0 += __shfl_xor_sync(~0u, db0, o);
        da1 += __shfl_xor_sync(~0u, da1, o); db1 += __shfl_xor_sync(~0u, db1, o);
        da2 += __shfl_xor_sync(~0u, da2, o); db2 += __shfl_xor_sync(~0u, db2, o);
        da3 += __shfl_xor_sync(~0u, da3, o); db3 += __shfl_xor_sync(~0u, db3, o);
        da4 += __shfl_xor_sync(~0u, da4, o); db4 += __shfl_xor_sync(~0u, db4, o);
        da5 += __shfl_xor_sync(~0u, da5, o); db5 += __shfl_xor_sync(~0u, db5, o);
    }
    if (lane == 0) {
        float da[6] = {da0, da1, da2, da3, da4, da5};
        float db[6] = {db0, db1, db2, db3, db4, db5};
#pragma unroll
        for (int h = 0; h < 6; h++) {
            float x = da[h] + dt_bias[h];
            float sp = (x > 20.f) ? x : log1pf(expf(x));
            gdec[gw * H_ + h] = -expf(A_log[h]) * sp;
            beta[gw * H_ + h] = 1.f / (1.f + expf(-db[h]));
        }
    }
}

// ---------------- gated delta rule scan ----------------
// 96 CTAs = B*H*NSL, 512 threads (16 warps). Thread (vl = tid>>3, kseg = tid&7)
// owns S[kseg*32 .. kseg*32+31][vl] as 16 packed f32x2 registers. k/q staged in
// smem as segment-padded rows (stride 36 floats per 32-dim segment -> the 8 kseg
// LDS.128 addresses land on 8 distinct 4-bank groups, conflict-free). Packed
// pairs loaded directly as ulonglong2 (no mov-packing); k cached in registers
// across both inner loops. Reduction over 8 ksegs via shfl_xor(1,2,4).
__global__ __launch_bounds__(512, 1)
void delta_scan(const float* __restrict__ q, const float* __restrict__ k,
                const float* __restrict__ v, const float* __restrict__ g,
                const float* __restrict__ beta, float* __restrict__ o) {
    __shared__ __align__(16) float ks[TOKB][288];
    __shared__ __align__(16) float qs[TOKB][288];
    __shared__ float vs[TOKB][DVS];
    __shared__ float egs[TOKB];
    __shared__ float bts[TOKB];

    const int bi = blockIdx.x;
    const int s = bi & 7;
    const int h = (bi >> 3) % H_;
    const int b = bi / (H_ * NSL);
    const int tid = threadIdx.x;
    const int vl = tid >> 3, kseg = tid & 7;

    unsigned long long S[16];
#pragma unroll
    for (int m = 0; m < 16; m++) S[m] = 0ull;

    for (int t0 = 0; t0 < T_; t0 += TOKB) {
        // ---- stage 8 tokens (k/q segment-padded, v, scalars) ----
#pragma unroll
        for (int i = 0; i < 4; i++) {
            int e = i * 512 + tid;
            int tt = e >> 8, d = e & 255;
            int si = (d >> 5) * 36 + (d & 31);
            size_t base = ((size_t)(b * T_ + t0 + tt) * H_ + h) * DKH;
            ks[tt][si] = k[base + d];
            qs[tt][si] = q[base + d];
        }
        {
            int tt = tid >> 6, vle = tid & 63;
            vs[tt][vle] = v[((size_t)(b * T_ + t0 + tt) * H_ + h) * DVH + s * DVS + vle];
        }
        if (tid < TOKB) {
            size_t gi = (size_t)(b * T_ + t0 + tid) * H_ + h;
            egs[tid] = expf(g[gi]);
            bts[tid] = beta[gi];
        }
        __syncthreads();

#pragma unroll 1
        for (int tt = 0; tt < TOKB; tt++) {
            const float eg = egs[tt], bt = bts[tt], vv = vs[tt][vl];
            const ulonglong2* kp = (const ulonglong2*)&ks[tt][kseg * 36];
            const ulonglong2* qp = (const ulonglong2*)&qs[tt][kseg * 36];

            // pred_partial = k . S_old  (cache k in registers)
            ulonglong2 kc[8];
            unsigned long long a0 = 0ull, a1 = 0ull;
#pragma unroll
            for (int m = 0; m < 8; m++) {
                kc[m] = kp[m];
                a0 = fma2u(kc[m].x, S[2 * m], a0);
                a1 = fma2u(kc[m].y, S[2 * m + 1], a1);
            }
            float2 f0 = up2(a0), f1 = up2(a1);
            float pred = f0.x + f0.y + f1.x + f1.y;
            pred += __shfl_xor_sync(0xffffffffu, pred, 1);
            pred += __shfl_xor_sync(0xffffffffu, pred, 2);
            pred += __shfl_xor_sync(0xffffffffu, pred, 4);
            pred *= eg;
            const float delta = (vv - pred) * bt;

            // S = eg*S + k*delta ; out = q . S_new
            const unsigned long long eg2 = pk2(eg, eg), d2 = pk2(delta, delta);
            unsigned long long o0 = 0ull, o1 = 0ull;
#pragma unroll
            for (int m = 0; m < 8; m++) {
                ulonglong2 qu = qp[m];
                unsigned long long s0 = fma2u(kc[m].x, d2, mul2u(eg2, S[2 * m]));
                unsigned long long s1 = fma2u(kc[m].y, d2, mul2u(eg2, S[2 * m + 1]));
                S[2 * m] = s0;
                S[2 * m + 1] = s1;
                o0 = fma2u(qu.x, s0, o0);
                o1 = fma2u(qu.y, s1, o1);
            }
            float2 g0 = up2(o0), g1 = up2(o1);
            float ov = g0.x + g0.y + g1.x + g1.y;
            ov += __shfl_xor_sync(0xffffffffu, ov, 1);
            ov += __shfl_xor_sync(0xffffffffu, ov, 2);
            ov += __shfl_xor_sync(0xffffffffu, ov, 4);
            if (kseg == 0)
                o[((size_t)(b * T_ + t0 + tt) * H_ + h) * DVH + s * DVS + vl] = ov;
        }
        __syncthreads();
    }
}

// ---------------- RMSNorm * weight * silu(gate) -> bf16 hi/lo split ----------------
__global__ void norm_gate(const float* __restrict__ o, const float* __restrict__ gate,
                          const float* __restrict__ nw,
                          __nv_bfloat16* __restrict__ yh, __nv_bfloat16* __restrict__ yl) {
    int gw = (blockIdx.x * 256 + threadIdx.x) >> 5;
    int lane = threadIdx.x & 31;
    size_t base = (size_t)gw * DVH;
    float4 v[4];
    float ss = 0.f;
#pragma unroll
    for (int i = 0; i < 4; i++) {
        v[i] = *(const float4*)(o + base + (lane + i * 32) * 4);
        ss += v[i].x * v[i].x + v[i].y * v[i].y + v[i].z * v[i].z + v[i].w * v[i].w;
    }
#pragma unroll
    for (int off = 16; off; off >>= 1) ss += __shfl_xor_sync(0xffffffffu, ss, off);
    float r = rsqrtf(ss * (1.f / 512.f) + 1e-5f);
#pragma unroll
    for (int i = 0; i < 4; i++) {
        int d4 = (lane + i * 32) * 4;
        float4 gt = *(const float4*)(gate + base + d4);
        float4 w = *(const float4*)(nw + d4);
        float o0 = v[i].x * r * w.x * (gt.x / (1.f + expf(-gt.x)));
        float o1 = v[i].y * r * w.y * (gt.y / (1.f + expf(-gt.y)));
        float o2 = v[i].z * r * w.z * (gt.z / (1.f + expf(-gt.z)));
        float o3 = v[i].w * r * w.w * (gt.w / (1.f + expf(-gt.w)));
        __nv_bfloat16 h0 = __float2bfloat16(o0), h1 = __float2bfloat16(o1);
        __nv_bfloat16 h2 = __float2bfloat16(o2), h3 = __float2bfloat16(o3);
        __nv_bfloat162* hp = (__nv_bfloat162*)(yh + base + d4);
        __nv_bfloat162* lp = (__nv_bfloat162*)(yl + base + d4);
        hp[0] = __nv_bfloat162(h0, h1);
        hp[1] = __nv_bfloat162(h2, h3);
        lp[0] = __nv_bfloat162(__float2bfloat16(o0 - __bfloat162float(h0)),
                               __float2bfloat16(o1 - __bfloat162float(h1)));
        lp[1] = __nv_bfloat162(__float2bfloat16(o2 - __bfloat162float(h2)),
                               __float2bfloat16(o3 - __bfloat162float(h3)));
    }
}

// ---------------- launch ----------------
extern "C" void kernel_launch(void* const* d_in, const int* in_sizes, int n_in,
                              void* d_out, int out_size) {
    const float* hid  = (const float*)d_in[0];
    const float* Wq   = (const float*)d_in[1];
    const float* Wk   = (const float*)d_in[2];
    const float* Wv   = (const float*)d_in[3];
    const float* Wa   = (const float*)d_in[4];
    const float* Wb   = (const float*)d_in[5];
    const float* Wg   = (const float*)d_in[6];
    const float* Wo   = (const float*)d_in[7];
    const float* cwq  = (const float*)d_in[8];
    const float* cwk  = (const float*)d_in[9];
    const float* cwv  = (const float*)d_in[10];
    const float* Alog = (const float*)d_in[11];
    const float* dtb  = (const float*)d_in[12];
    const float* nw   = (const float*)d_in[13];

    float *xq, *xk, *xv, *gt, *qn, *kn, *vn, *od, *gd, *bt, *wat, *wbt;
    __nv_bfloat16 *ahi, *alo, *yhi, *ylo, *wqh, *wql, *wkh, *wkl, *wvh, *wvl, *wgh, *wgl, *woh, *wol;
    cudaGetSymbolAddress((void**)&xq, g_xq);
    cudaGetSymbolAddress((void**)&xk, g_xk);
    cudaGetSymbolAddress((void**)&xv, g_xv);
    cudaGetSymbolAddress((void**)&gt, g_gt);
    cudaGetSymbolAddress((void**)&qn, g_qn);
    cudaGetSymbolAddress((void**)&kn, g_kn);
    cudaGetSymbolAddress((void**)&vn, g_vn);
    cudaGetSymbolAddress((void**)&od, g_od);
    cudaGetSymbolAddress((void**)&gd, g_gd);
    cudaGetSymbolAddress((void**)&bt, g_bt);
    cudaGetSymbolAddress((void**)&wat, g_wat);
    cudaGetSymbolAddress((void**)&wbt, g_wbt);
    cudaGetSymbolAddress((void**)&ahi, g_ahi);
    cudaGetSymbolAddress((void**)&alo, g_alo);
    cudaGetSymbolAddress((void**)&yhi, g_yhi);
    cudaGetSymbolAddress((void**)&ylo, g_ylo);
    cudaGetSymbolAddress((void**)&wqh, g_wqh);
    cudaGetSymbolAddress((void**)&wql, g_wql);
    cudaGetSymbolAddress((void**)&wkh, g_wkh);
    cudaGetSymbolAddress((void**)&wkl, g_wkl);
    cudaGetSymbolAddress((void**)&wvh, g_wvh);
    cudaGetSymbolAddress((void**)&wvl, g_wvl);
    cudaGetSymbolAddress((void**)&wgh, g_wgh);
    cudaGetSymbolAddress((void**)&wgl, g_wgl);
    cudaGetSymbolAddress((void**)&woh, g_woh);
    cudaGetSymbolAddress((void**)&wol, g_wol);

    cudaFuncSetAttribute(gemm_bf16x3, cudaFuncAttributeMaxDynamicSharedMemorySize, GEMM_SMEM);

    // bf16 splits: activations + weights (transposed to [N,K])
    split4<<<(ROWS_ * HID_ / 4) / 256, 256>>>(hid, ahi, alo);
    tsplit<<<dim3(KEYD / 32, HID_ / 32), 256>>>(Wq, wqh, wql, HID_, KEYD);
    tsplit<<<dim3(KEYD / 32, HID_ / 32), 256>>>(Wk, wkh, wkl, HID_, KEYD);
    tsplit<<<dim3(VALD / 32, HID_ / 32), 256>>>(Wv, wvh, wvl, HID_, VALD);
    tsplit<<<dim3(VALD / 32, HID_ / 32), 256>>>(Wg, wgh, wgl, HID_, VALD);
    tsplit<<<dim3(HID_ / 32, VALD / 32), 256>>>(Wo, woh, wol, VALD, HID_);

    // tensor-core projections (HMMA mma.sync path)
    gemm_bf16x3<<<dim3(KEYD / 128, ROWS_ / 128), 256, GEMM_SMEM>>>(ahi, alo, wqh, wql, xq, ROWS_, KEYD, HID_);
    gemm_bf16x3<<<dim3(KEYD / 128, ROWS_ / 128), 256, GEMM_SMEM>>>(ahi, alo, wkh, wkl, xk, ROWS_, KEYD, HID_);
    gemm_bf16x3<<<dim3(VALD / 128, ROWS_ / 128), 256, GEMM_SMEM>>>(ahi, alo, wvh, wvl, xv, ROWS_, VALD, HID_);
    gemm_bf16x3<<<dim3(VALD / 128, ROWS_ / 128), 256, GEMM_SMEM>>>(ahi, alo, wgh, wgl, gt, ROWS_, VALD, HID_);

    // beta / decay
    transpose6<<<(H_ * HID_) / 256, 256>>>(Wa, Wb, wat, wbt);
    proj_ab<<<(ROWS_ * 32) / 256, 256>>>(hid, wat, wbt, Alog, dtb, gd, bt);

    // conv + silu
    conv_silu_k<<<(ROWS_ * KEYD) / 256, 256>>>(xq, cwq, qn, KEYD);
    conv_silu_k<<<(ROWS_ * KEYD) / 256, 256>>>(xk, cwk, kn, KEYD);
    conv_silu_k<<<(ROWS_ * VALD) / 256, 256>>>(xv, cwv, vn, VALD);

    // l2 norms (q also scaled by dk^-0.5 = 1/16)
    l2norm_k<<<(ROWS_ * H_ * 32) / 256, 256>>>(qn, 0.0625f);
    l2norm_k<<<(ROWS_ * H_ * 32) / 256, 256>>>(kn, 1.0f);

    // sequential gated delta rule
    delta_scan<<<B_ * H_ * NSL, 512>>>(qn, kn, vn, gd, bt, od);

    // rmsnorm * weight * silu(gate) -> bf16 hi/lo
    norm_gate<<<(ROWS_ * H_ * 32) / 256, 256>>>(od, gt, nw, yhi, ylo);

    // output projection -> d_out
    gemm_bf16x3<<<dim3(HID_ / 128, ROWS_ / 128), 256, GEMM_SMEM>>>(yhi, ylo, woh, wol, (float*)d_out, ROWS_, HID_, VALD);
}

// round 7
// speedup vs baseline: 1.0500x; 1.0500x over previous
#include <cuda_runtime.h>
#include <cuda_fp16.h>
#include <cuda_bf16.h>
#include <math.h>
#include <stdint.h>

// ---------------- problem constants ----------------
#define B_ 2
#define T_ 4096
#define HID_ 2048
#define H_ 6
#define DKH 256
#define DVH 512
#define KEYD 1536
#define VALD 3072
#define ROWS_ (B_ * T_)          // 8192
#define DVS 64                   // dv slice per scan CTA
#define NSL 8                    // 512/64
#define TOKB 8                   // tokens staged per scan round
#define LOSCALE 2048.0f
#define INVLOSCALE (1.0f / 2048.0f)

// ---------------- scratch (device globals; no allocation allowed) ----------------
__device__ float g_xq[ROWS_ * KEYD];
__device__ float g_xk[ROWS_ * KEYD];
__device__ float g_xv[ROWS_ * VALD];
__device__ float g_gt[ROWS_ * VALD];
__device__ float g_qn[ROWS_ * KEYD];
__device__ float g_kn[ROWS_ * KEYD];
__device__ float g_vn[ROWS_ * VALD];
__device__ float g_od[ROWS_ * VALD];
__device__ float g_gd[ROWS_ * H_];
__device__ float g_bt[ROWS_ * H_];
__device__ float g_wat[H_ * HID_];
__device__ float g_wbt[H_ * HID_];
// fp16 split buffers (lo scaled by 2^11)
__device__ __half g_ah[ROWS_ * HID_];
__device__ __half g_al[ROWS_ * HID_];
__device__ __half g_yh[ROWS_ * VALD];
__device__ __half g_yl[ROWS_ * VALD];
__device__ __half g_wqkh[2 * KEYD * HID_];   // Wq rows then Wk rows, [N,K]
__device__ __half g_wqkl[2 * KEYD * HID_];
__device__ __half g_wvgh[2 * VALD * HID_];   // Wv rows then Wg rows
__device__ __half g_wvgl[2 * VALD * HID_];
__device__ __half g_woh[HID_ * VALD];
__device__ __half g_wol[HID_ * VALD];

// ---------------- packed f32x2 helpers ----------------
__device__ __forceinline__ unsigned long long pk2(float x, float y) {
    unsigned long long r;
    asm("mov.b64 %0, {%1, %2};" : "=l"(r) : "f"(x), "f"(y));
    return r;
}
__device__ __forceinline__ float2 up2(unsigned long long v) {
    float2 r;
    asm("mov.b64 {%0, %1}, %2;" : "=f"(r.x), "=f"(r.y) : "l"(v));
    return r;
}
__device__ __forceinline__ unsigned long long fma2u(unsigned long long a, unsigned long long b, unsigned long long c) {
    unsigned long long d;
    asm("fma.rn.f32x2 %0, %1, %2, %3;" : "=l"(d) : "l"(a), "l"(b), "l"(c));
    return d;
}
__device__ __forceinline__ unsigned long long mul2u(unsigned long long a, unsigned long long b) {
    unsigned long long d;
    asm("mul.rn.f32x2 %0, %1, %2;" : "=l"(d) : "l"(a), "l"(b));
    return d;
}

// ---------------- mma.sync / ldmatrix / cp.async helpers ----------------
__device__ __forceinline__ uint32_t smem_u32(const void* p) {
    uint32_t a;
    asm("{ .reg .u64 t; cvta.to.shared.u64 t, %1; cvt.u32.u64 %0, t; }" : "=r"(a) : "l"(p));
    return a;
}
__device__ __forceinline__ void ldm_x4(uint32_t* r, uint32_t addr) {
    asm volatile("ldmatrix.sync.aligned.m8n8.x4.shared.b16 {%0,%1,%2,%3}, [%4];"
                 : "=r"(r[0]), "=r"(r[1]), "=r"(r[2]), "=r"(r[3]) : "r"(addr));
}
// f16 inputs, f32 accumulate (main product)
__device__ __forceinline__ void mma_hf32(float* c, const uint32_t* a, const uint32_t* b) {
    asm volatile("mma.sync.aligned.m16n8k16.row.col.f32.f16.f16.f32 "
                 "{%0,%1,%2,%3}, {%4,%5,%6,%7}, {%8,%9}, {%0,%1,%2,%3};"
                 : "+f"(c[0]), "+f"(c[1]), "+f"(c[2]), "+f"(c[3])
                 : "r"(a[0]), "r"(a[1]), "r"(a[2]), "r"(a[3]), "r"(b[0]), "r"(b[1]));
}
// f16 inputs, f16 accumulate (correction products; possibly double-rate)
__device__ __forceinline__ void mma_hf16(uint32_t* c, const uint32_t* a, const uint32_t* b) {
    asm volatile("mma.sync.aligned.m16n8k16.row.col.f16.f16.f16.f16 "
                 "{%0,%1}, {%2,%3,%4,%5}, {%6,%7}, {%0,%1};"
                 : "+r"(c[0]), "+r"(c[1])
                 : "r"(a[0]), "r"(a[1]), "r"(a[2]), "r"(a[3]), "r"(b[0]), "r"(b[1]));
}
__device__ __forceinline__ void cp16(uint32_t sm, const void* gp) {
    asm volatile("cp.async.cg.shared.global [%0], [%1], 16;" :: "r"(sm), "l"(gp));
}
#define CP_COMMIT() asm volatile("cp.async.commit_group;" ::: "memory")
#define CP_WAIT0()  asm volatile("cp.async.wait_group 0;" ::: "memory")

// ---------------- fp16-split HMMA GEMM ----------------
// C[M,N] = A[M,K] @ B^T; A row-major (hi + 2^11-scaled lo fp16), B [N,K] likewise.
// P_main = Ah*Bh (f32 acc); corrections (Al'*Bh + Ah*Bl') accumulate in ONE f16
// accumulator, merged at epilogue with *2^-11.
// CTA 128x128, 256 threads, warp tile 64x32, K-chunk 64, cp.async double buffer.
// SMEM rows padded to 72 halves (144B) -> conflict-free ldmatrix.
// Fused-output: columns [0,splitN) -> C0, [splitN,N) -> C1; both row-stride splitN.
#define GTILE 18432            // 128 rows * 144 B
#define GBUF  73728            // 4 tiles
#define GEMM_SMEM 147456       // 2 buffers

__global__ __launch_bounds__(256, 1)
void gemm_hx3(const __half* __restrict__ Ahi, const __half* __restrict__ Alo,
              const __half* __restrict__ Bhi, const __half* __restrict__ Blo,
              float* __restrict__ C0, float* __restrict__ C1,
              int splitN, int M, int N, int K) {
    extern __shared__ __align__(16) char smem[];
    const uint32_t sbase = smem_u32(smem);
    const int tid = threadIdx.x, lane = tid & 31, wid = tid >> 5;
    const int wm = wid & 1, wn = wid >> 1;      // 2 x 4 warp grid
    const int brow = blockIdx.y * 128, bcol = blockIdx.x * 128;

    const __half* srcs[4] = {Ahi, Alo, Bhi, Blo};
    const int row0[4] = {brow, brow, bcol, bcol};

    float accF[4][4][4];
    uint32_t accH[4][4][2];
#pragma unroll
    for (int i = 0; i < 4; i++)
#pragma unroll
        for (int j = 0; j < 4; j++) {
#pragma unroll
            for (int l = 0; l < 4; l++) accF[i][j][l] = 0.f;
            accH[i][j][0] = 0u; accH[i][j][1] = 0u;
        }

    const int r_ = tid >> 3, c8_ = (tid & 7) * 8;   // per-thread load coords

    // prologue: chunk 0 -> buf 0
#pragma unroll
    for (int ts = 0; ts < 4; ts++) {
        const __half* sp = srcs[ts] + (size_t)(row0[ts] + r_) * K + c8_;
        uint32_t tb = sbase + ts * GTILE + r_ * 144 + c8_ * 2;
#pragma unroll
        for (int i = 0; i < 4; i++)
            cp16(tb + i * 32 * 144, sp + (size_t)(i * 32) * K);
    }
    CP_COMMIT();
    CP_WAIT0();
    __syncthreads();

    const int numT = K >> 6;
    const uint32_t a_lane = (lane & 15) * 144 + (lane >> 4) * 16;
    // B x4: lanes 0-7 rows n0..n0+7 k0 | 8-15 same rows k1 | 16-23 rows +8 k0 | 24-31 k1
    const uint32_t b_lane4 = ((lane & 7) + (lane >> 4) * 8) * 144 + ((lane >> 3) & 1) * 16;

    for (int c = 0; c < numT; c++) {
        const int b = c & 1;
        if (c + 1 < numT) {
            const int kc = (c + 1) << 6, nb = b ^ 1;
#pragma unroll
            for (int ts = 0; ts < 4; ts++) {
                const __half* sp = srcs[ts] + (size_t)(row0[ts] + r_) * K + kc + c8_;
                uint32_t tb = sbase + nb * GBUF + ts * GTILE + r_ * 144 + c8_ * 2;
#pragma unroll
                for (int i = 0; i < 4; i++)
                    cp16(tb + i * 32 * 144, sp + (size_t)(i * 32) * K);
            }
            CP_COMMIT();
        }
        const uint32_t aH = sbase + b * GBUF + wm * 64 * 144;
        const uint32_t aL = aH + GTILE;
        const uint32_t bH = sbase + b * GBUF + 2 * GTILE + wn * 32 * 144;
        const uint32_t bL = bH + GTILE;
#pragma unroll
        for (int ks = 0; ks < 4; ks++) {
            const uint32_t acol = ks * 32 + a_lane;
            const uint32_t bcol2 = ks * 32 + b_lane4;
            uint32_t fAH[4][4], fAL[4][4], fBH[4][2], fBL[4][2];
#pragma unroll
            for (int mt = 0; mt < 4; mt++) {
                ldm_x4(fAH[mt], aH + mt * 16 * 144 + acol);
                ldm_x4(fAL[mt], aL + mt * 16 * 144 + acol);
            }
#pragma unroll
            for (int p = 0; p < 2; p++) {
                uint32_t r4[4];
                ldm_x4(r4, bH + p * 16 * 144 + bcol2);
                fBH[2 * p][0] = r4[0]; fBH[2 * p][1] = r4[1];
                fBH[2 * p + 1][0] = r4[2]; fBH[2 * p + 1][1] = r4[3];
                ldm_x4(r4, bL + p * 16 * 144 + bcol2);
                fBL[2 * p][0] = r4[0]; fBL[2 * p][1] = r4[1];
                fBL[2 * p + 1][0] = r4[2]; fBL[2 * p + 1][1] = r4[3];
            }
#pragma unroll
            for (int mt = 0; mt < 4; mt++)
#pragma unroll
                for (int nt = 0; nt < 4; nt++) {
                    mma_hf32(accF[mt][nt], fAH[mt], fBH[nt]);
                    mma_hf16(accH[mt][nt], fAL[mt], fBH[nt]);
                    mma_hf16(accH[mt][nt], fAH[mt], fBL[nt]);
                }
        }
        CP_WAIT0();
        __syncthreads();
    }

    // epilogue: merge f32 main + f16 corrections, route to C0/C1
    float* Cp;
    int ccol0;
    if (bcol < splitN) { Cp = C0; ccol0 = bcol; }
    else               { Cp = C1; ccol0 = bcol - splitN; }
    const int r0 = lane >> 2, cc = (lane & 3) * 2;
#pragma unroll
    for (int mt = 0; mt < 4; mt++)
#pragma unroll
        for (int nt = 0; nt < 4; nt++) {
            float2 lo01 = __half22float2(*(__half2*)&accH[mt][nt][0]);
            float2 lo23 = __half22float2(*(__half2*)&accH[mt][nt][1]);
            size_t base = (size_t)(brow + wm * 64 + mt * 16 + r0) * splitN + ccol0 + wn * 32 + nt * 8 + cc;
            *(float2*)&Cp[base] = make_float2(accF[mt][nt][0] + lo01.x * INVLOSCALE,
                                              accF[mt][nt][1] + lo01.y * INVLOSCALE);
            *(float2*)&Cp[base + 8 * (size_t)splitN] = make_float2(accF[mt][nt][2] + lo23.x * INVLOSCALE,
                                                                   accF[mt][nt][3] + lo23.y * INVLOSCALE);
        }
}

// ---------------- fp32 -> fp16 hi/lo split (lo scaled by 2^11) ----------------
__global__ void split4(const float* __restrict__ x, __half* __restrict__ xh,
                       __half* __restrict__ xl) {
    int i4 = blockIdx.x * 256 + threadIdx.x;
    float4 v = ((const float4*)x)[i4];
    __half h0 = __float2half_rn(v.x), h1 = __float2half_rn(v.y);
    __half h2 = __float2half_rn(v.z), h3 = __float2half_rn(v.w);
    __half l0 = __float2half_rn((v.x - __half2float(h0)) * LOSCALE);
    __half l1 = __float2half_rn((v.y - __half2float(h1)) * LOSCALE);
    __half l2 = __float2half_rn((v.z - __half2float(h2)) * LOSCALE);
    __half l3 = __float2half_rn((v.w - __half2float(h3)) * LOSCALE);
    __half2* hp = (__half2*)(xh + (size_t)i4 * 4);
    __half2* lp = (__half2*)(xl + (size_t)i4 * 4);
    hp[0] = __halves2half2(h0, h1); hp[1] = __halves2half2(h2, h3);
    lp[0] = __halves2half2(l0, l1); lp[1] = __halves2half2(l2, l3);
}

// ---------------- weight transpose + split: W[K,N] -> Wh/Wl [N,K] fp16 ----------------
__global__ void tsplit(const float* __restrict__ W, __half* __restrict__ Wh,
                       __half* __restrict__ Wl, int K, int N) {
    __shared__ float tile[32][33];
    int n0 = blockIdx.x * 32, k0 = blockIdx.y * 32;
    int tx = threadIdx.x & 31, ty = threadIdx.x >> 5;   // 32x8
#pragma unroll
    for (int i = 0; i < 4; i++) {
        int k = k0 + ty + i * 8;
        tile[ty + i * 8][tx] = W[(size_t)k * N + n0 + tx];
    }
    __syncthreads();
#pragma unroll
    for (int i = 0; i < 4; i++) {
        int n = n0 + ty + i * 8;
        float x = tile[tx][ty + i * 8];
        __half h = __float2half_rn(x);
        Wh[(size_t)n * K + k0 + tx] = h;
        Wl[(size_t)n * K + k0 + tx] = __float2half_rn((x - __half2float(h)) * LOSCALE);
    }
}

// ---------------- causal depthwise conv (K=4) + SiLU ----------------
__global__ void conv_silu_k(const float* __restrict__ x, const float* __restrict__ w,
                            float* __restrict__ y, int D) {
    int idx = blockIdx.x * 256 + threadIdx.x;
    int d = idx % D;
    int t = (idx / D) & (T_ - 1);
    float4 wv = *(const float4*)(w + d * 4);
    float acc = x[idx] * wv.w;
    if (t >= 1) acc += x[idx - D] * wv.z;
    if (t >= 2) acc += x[idx - 2 * D] * wv.y;
    if (t >= 3) acc += x[idx - 3 * D] * wv.x;
    y[idx] = acc / (1.f + expf(-acc));
}

// ---------------- per-(b,t,h) L2 norm over 256, in place, times scale ----------------
__global__ void l2norm_k(float* __restrict__ x, float scale) {
    int gw = (blockIdx.x * 256 + threadIdx.x) >> 5;
    int lane = threadIdx.x & 31;
    float* row = x + (size_t)gw * DKH;
    float4 v0 = *(const float4*)(row + lane * 8);
    float4 v1 = *(const float4*)(row + lane * 8 + 4);
    float ss = v0.x * v0.x + v0.y * v0.y + v0.z * v0.z + v0.w * v0.w +
               v1.x * v1.x + v1.y * v1.y + v1.z * v1.z + v1.w * v1.w;
#pragma unroll
    for (int o = 16; o; o >>= 1) ss += __shfl_xor_sync(0xffffffffu, ss, o);
    float r = rsqrtf(ss) * scale;
    v0.x *= r; v0.y *= r; v0.z *= r; v0.w *= r;
    v1.x *= r; v1.y *= r; v1.z *= r; v1.w *= r;
    *(float4*)(row + lane * 8) = v0;
    *(float4*)(row + lane * 8 + 4) = v1;
}

// ---------------- transpose Wa/Wb (2048x6 -> 6x2048) ----------------
__global__ void transpose6(const float* __restrict__ Wa, const float* __restrict__ Wb,
                           float* __restrict__ WaT, float* __restrict__ WbT) {
    int i = blockIdx.x * 256 + threadIdx.x;
    int c = i / H_, h = i % H_;
    WaT[h * HID_ + c] = Wa[i];
    WbT[h * HID_ + c] = Wb[i];
}

// ---------------- beta / decay projection ----------------
__global__ void proj_ab(const float* __restrict__ hid, const float* __restrict__ WaT,
                        const float* __restrict__ WbT, const float* __restrict__ A_log,
                        const float* __restrict__ dt_bias,
                        float* __restrict__ gdec, float* __restrict__ beta) {
    int gw = (blockIdx.x * 256 + threadIdx.x) >> 5;
    int lane = threadIdx.x & 31;
    const float* hr = hid + (size_t)gw * HID_;
    float da0 = 0, da1 = 0, da2 = 0, da3 = 0, da4 = 0, da5 = 0;
    float db0 = 0, db1 = 0, db2 = 0, db3 = 0, db4 = 0, db5 = 0;
    for (int c = lane; c < HID_; c += 32) {
        float hv = hr[c];
        da0 += hv * WaT[0 * HID_ + c]; db0 += hv * WbT[0 * HID_ + c];
        da1 += hv * WaT[1 * HID_ + c]; db1 += hv * WbT[1 * HID_ + c];
        da2 += hv * WaT[2 * HID_ + c]; db2 += hv * WbT[2 * HID_ + c];
        da3 += hv * WaT[3 * HID_ + c]; db3 += hv * WbT[3 * HID_ + c];
        da4 += hv * WaT[4 * HID_ + c]; db4 += hv * WbT[4 * HID_ + c];
        da5 += hv * WaT[5 * HID_ + c]; db5 += hv * WbT[5 * HID_ + c];
    }
#pragma unroll
    for (int o = 16; o; o >>= 1) {
        da0 += __shfl_xor_sync(~0u, da0, o); db0 += __shfl_xor_sync(~0u, db0, o);
        da1 += __shfl_xor_sync(~0u, da1, o); db1 += __shfl_xor_sync(~0u, db1, o);
        da2 += __shfl_xor_sync(~0u, da2, o); db2 += __shfl_xor_sync(~0u, db2, o);
        da3 += __shfl_xor_sync(~0u, da3, o); db3 += __shfl_xor_sync(~0u, db3, o);
        da4 += __shfl_xor_sync(~0u, da4, o); db4 += __shfl_xor_sync(~0u, db4, o);
        da5 += __shfl_xor_sync(~0u, da5, o); db5 += __shfl_xor_sync(~0u, db5, o);
    }
    if (lane == 0) {
        float da[6] = {da0, da1, da2, da3, da4, da5};
        float db[6] = {db0, db1, db2, db3, db4, db5};
#pragma unroll
        for (int h = 0; h < 6; h++) {
            float x = da[h] + dt_bias[h];
            float sp = (x > 20.f) ? x : log1pf(expf(x));
            gdec[gw * H_ + h] = -expf(A_log[h]) * sp;
            beta[gw * H_ + h] = 1.f / (1.f + expf(-db[h]));
        }
    }
}

// ---------------- gated delta rule scan (R4 known-good version) ----------------
__global__ __launch_bounds__(256, 1)
void delta_scan(const float* __restrict__ q, const float* __restrict__ k,
                const float* __restrict__ v, const float* __restrict__ g,
                const float* __restrict__ beta, float* __restrict__ o) {
    __shared__ __align__(16) float ks[TOKB][272];
    __shared__ __align__(16) float qs[TOKB][272];
    __shared__ float vs[TOKB][DVS];
    __shared__ float egs[TOKB];
    __shared__ float bts[TOKB];

    const int bi = blockIdx.x;
    const int s = bi & 7;
    const int h = (bi >> 3) % H_;
    const int b = bi / (H_ * NSL);
    const int tid = threadIdx.x;
    const int vl = tid >> 2, kseg = tid & 3;
    const int sidx = (tid >> 6) * 68 + (tid & 63);

    unsigned long long S[32];
#pragma unroll
    for (int m = 0; m < 32; m++) S[m] = 0ull;

    for (int t0 = 0; t0 < T_; t0 += TOKB) {
#pragma unroll
        for (int tt = 0; tt < TOKB; tt++) {
            size_t base = ((size_t)(b * T_ + t0 + tt) * H_ + h) * DKH;
            ks[tt][sidx] = k[base + tid];
            qs[tt][sidx] = q[base + tid];
        }
#pragma unroll
        for (int i = 0; i < 2; i++) {
            int ee = i * 256 + tid;
            int tt = ee >> 6, vle = ee & 63;
            vs[tt][vle] = v[((size_t)(b * T_ + t0 + tt) * H_ + h) * DVH + s * DVS + vle];
        }
        if (tid < TOKB) {
            size_t gi = (size_t)(b * T_ + t0 + tid) * H_ + h;
            egs[tid] = expf(g[gi]);
            bts[tid] = beta[gi];
        }
        __syncthreads();

#pragma unroll 1
        for (int tt = 0; tt < TOKB; tt++) {
            float eg = egs[tt], bt = bts[tt], vv = vs[tt][vl];
            const float4* kp = (const float4*)&ks[tt][kseg * 68];
            const float4* qp = (const float4*)&qs[tt][kseg * 68];

            unsigned long long a0 = 0ull, a1 = 0ull;
#pragma unroll
            for (int m4 = 0; m4 < 16; m4++) {
                float4 k4 = kp[m4];
                a0 = fma2u(pk2(k4.x, k4.y), S[2 * m4], a0);
                a1 = fma2u(pk2(k4.z, k4.w), S[2 * m4 + 1], a1);
            }
            float2 f0 = up2(a0), f1 = up2(a1);
            float pred = f0.x + f0.y + f1.x + f1.y;
            pred += __shfl_xor_sync(0xffffffffu, pred, 1);
            pred += __shfl_xor_sync(0xffffffffu, pred, 2);
            pred *= eg;
            float delta = (vv - pred) * bt;

            unsigned long long eg2 = pk2(eg, eg), d2 = pk2(delta, delta);
            unsigned long long o0 = 0ull, o1 = 0ull;
#pragma unroll
            for (int m4 = 0; m4 < 16; m4++) {
                float4 k4 = kp[m4];
                float4 q4 = qp[m4];
                unsigned long long s0 = fma2u(pk2(k4.x, k4.y), d2, mul2u(eg2, S[2 * m4]));
                unsigned long long s1 = fma2u(pk2(k4.z, k4.w), d2, mul2u(eg2, S[2 * m4 + 1]));
                S[2 * m4] = s0;
                S[2 * m4 + 1] = s1;
                o0 = fma2u(pk2(q4.x, q4.y), s0, o0);
                o1 = fma2u(pk2(q4.z, q4.w), s1, o1);
            }
            float2 g0 = up2(o0), g1 = up2(o1);
            float ov = g0.x + g0.y + g1.x + g1.y;
            ov += __shfl_xor_sync(0xffffffffu, ov, 1);
            ov += __shfl_xor_sync(0xffffffffu, ov, 2);
            if (kseg == 0)
                o[((size_t)(b * T_ + t0 + tt) * H_ + h) * DVH + s * DVS + vl] = ov;
        }
        __syncthreads();
    }
}

// ---------------- RMSNorm * weight * silu(gate) -> fp16 hi/lo split ----------------
__global__ void norm_gate(const float* __restrict__ o, const float* __restrict__ gate,
                          const float* __restrict__ nw,
                          __half* __restrict__ yh, __half* __restrict__ yl) {
    int gw = (blockIdx.x * 256 + threadIdx.x) >> 5;
    int lane = threadIdx.x & 31;
    size_t base = (size_t)gw * DVH;
    float4 v[4];
    float ss = 0.f;
#pragma unroll
    for (int i = 0; i < 4; i++) {
        v[i] = *(const float4*)(o + base + (lane + i * 32) * 4);
        ss += v[i].x * v[i].x + v[i].y * v[i].y + v[i].z * v[i].z + v[i].w * v[i].w;
    }
#pragma unroll
    for (int off = 16; off; off >>= 1) ss += __shfl_xor_sync(0xffffffffu, ss, off);
    float r = rsqrtf(ss * (1.f / 512.f) + 1e-5f);
#pragma unroll
    for (int i = 0; i < 4; i++) {
        int d4 = (lane + i * 32) * 4;
        float4 gt = *(const float4*)(gate + base + d4);
        float4 w = *(const float4*)(nw + d4);
        float o0 = v[i].x * r * w.x * (gt.x / (1.f + expf(-gt.x)));
        float o1 = v[i].y * r * w.y * (gt.y / (1.f + expf(-gt.y)));
        float o2 = v[i].z * r * w.z * (gt.z / (1.f + expf(-gt.z)));
        float o3 = v[i].w * r * w.w * (gt.w / (1.f + expf(-gt.w)));
        __half h0 = __float2half_rn(o0), h1 = __float2half_rn(o1);
        __half h2 = __float2half_rn(o2), h3 = __float2half_rn(o3);
        __half2* hp = (__half2*)(yh + base + d4);
        __half2* lp = (__half2*)(yl + base + d4);
        hp[0] = __halves2half2(h0, h1);
        hp[1] = __halves2half2(h2, h3);
        lp[0] = __halves2half2(__float2half_rn((o0 - __half2float(h0)) * LOSCALE),
                               __float2half_rn((o1 - __half2float(h1)) * LOSCALE));
        lp[1] = __halves2half2(__float2half_rn((o2 - __half2float(h2)) * LOSCALE),
                               __float2half_rn((o3 - __half2float(h3)) * LOSCALE));
    }
}

// ---------------- launch ----------------
extern "C" void kernel_launch(void* const* d_in, const int* in_sizes, int n_in,
                              void* d_out, int out_size) {
    const float* hid  = (const float*)d_in[0];
    const float* Wq   = (const float*)d_in[1];
    const float* Wk   = (const float*)d_in[2];
    const float* Wv   = (const float*)d_in[3];
    const float* Wa   = (const float*)d_in[4];
    const float* Wb   = (const float*)d_in[5];
    const float* Wg   = (const float*)d_in[6];
    const float* Wo   = (const float*)d_in[7];
    const float* cwq  = (const float*)d_in[8];
    const float* cwk  = (const float*)d_in[9];
    const float* cwv  = (const float*)d_in[10];
    const float* Alog = (const float*)d_in[11];
    const float* dtb  = (const float*)d_in[12];
    const float* nw   = (const float*)d_in[13];

    float *xq, *xk, *xv, *gt, *qn, *kn, *vn, *od, *gd, *bt, *wat, *wbt;
    __half *ah, *al, *yh, *yl, *wqkh, *wqkl, *wvgh, *wvgl, *woh, *wol;
    cudaGetSymbolAddress((void**)&xq, g_xq);
    cudaGetSymbolAddress((void**)&xk, g_xk);
    cudaGetSymbolAddress((void**)&xv, g_xv);
    cudaGetSymbolAddress((void**)&gt, g_gt);
    cudaGetSymbolAddress((void**)&qn, g_qn);
    cudaGetSymbolAddress((void**)&kn, g_kn);
    cudaGetSymbolAddress((void**)&vn, g_vn);
    cudaGetSymbolAddress((void**)&od, g_od);
    cudaGetSymbolAddress((void**)&gd, g_gd);
    cudaGetSymbolAddress((void**)&bt, g_bt);
    cudaGetSymbolAddress((void**)&wat, g_wat);
    cudaGetSymbolAddress((void**)&wbt, g_wbt);
    cudaGetSymbolAddress((void**)&ah, g_ah);
    cudaGetSymbolAddress((void**)&al, g_al);
    cudaGetSymbolAddress((void**)&yh, g_yh);
    cudaGetSymbolAddress((void**)&yl, g_yl);
    cudaGetSymbolAddress((void**)&wqkh, g_wqkh);
    cudaGetSymbolAddress((void**)&wqkl, g_wqkl);
    cudaGetSymbolAddress((void**)&wvgh, g_wvgh);
    cudaGetSymbolAddress((void**)&wvgl, g_wvgl);
    cudaGetSymbolAddress((void**)&woh, g_woh);
    cudaGetSymbolAddress((void**)&wol, g_wol);

    cudaFuncSetAttribute(gemm_hx3, cudaFuncAttributeMaxDynamicSharedMemorySize, GEMM_SMEM);

    // fp16 splits: activations + weights (transposed to [N,K], fused slices)
    split4<<<(ROWS_ * HID_ / 4) / 256, 256>>>(hid, ah, al);
    tsplit<<<dim3(KEYD / 32, HID_ / 32), 256>>>(Wq, wqkh, wqkl, HID_, KEYD);
    tsplit<<<dim3(KEYD / 32, HID_ / 32), 256>>>(Wk, wqkh + (size_t)KEYD * HID_, wqkl + (size_t)KEYD * HID_, HID_, KEYD);
    tsplit<<<dim3(VALD / 32, HID_ / 32), 256>>>(Wv, wvgh, wvgl, HID_, VALD);
    tsplit<<<dim3(VALD / 32, HID_ / 32), 256>>>(Wg, wvgh + (size_t)VALD * HID_, wvgl + (size_t)VALD * HID_, HID_, VALD);
    tsplit<<<dim3(HID_ / 32, VALD / 32), 256>>>(Wo, woh, wol, VALD, HID_);

    // fused tensor-core projections: QK (N=3072), VG (N=6144)
    gemm_hx3<<<dim3(2 * KEYD / 128, ROWS_ / 128), 256, GEMM_SMEM>>>(ah, al, wqkh, wqkl, xq, xk, KEYD, ROWS_, 2 * KEYD, HID_);
    gemm_hx3<<<dim3(2 * VALD / 128, ROWS_ / 128), 256, GEMM_SMEM>>>(ah, al, wvgh, wvgl, xv, gt, VALD, ROWS_, 2 * VALD, HID_);

    // beta / decay
    transpose6<<<(H_ * HID_) / 256, 256>>>(Wa, Wb, wat, wbt);
    proj_ab<<<(ROWS_ * 32) / 256, 256>>>(hid, wat, wbt, Alog, dtb, gd, bt);

    // conv + silu
    conv_silu_k<<<(ROWS_ * KEYD) / 256, 256>>>(xq, cwq, qn, KEYD);
    conv_silu_k<<<(ROWS_ * KEYD) / 256, 256>>>(xk, cwk, kn, KEYD);
    conv_silu_k<<<(ROWS_ * VALD) / 256, 256>>>(xv, cwv, vn, VALD);

    // l2 norms (q also scaled by dk^-0.5 = 1/16)
    l2norm_k<<<(ROWS_ * H_ * 32) / 256, 256>>>(qn, 0.0625f);
    l2norm_k<<<(ROWS_ * H_ * 32) / 256, 256>>>(kn, 1.0f);

    // sequential gated delta rule
    delta_scan<<<B_ * H_ * NSL, 256>>>(qn, kn, vn, gd, bt, od);

    // rmsnorm * weight * silu(gate) -> fp16 hi/lo
    norm_gate<<<(ROWS_ * H_ * 32) / 256, 256>>>(od, gt, nw, yh, yl);

    // output projection -> d_out (unfused: splitN = N)
    gemm_hx3<<<dim3(HID_ / 128, ROWS_ / 128), 256, GEMM_SMEM>>>(yh, yl, woh, wol, (float*)d_out, (float*)d_out, HID_, ROWS_, HID_, VALD);
}

// round 8
// speedup vs baseline: 1.2094x; 1.1518x over previous
#include <cuda_runtime.h>
#include <cuda_fp16.h>
#include <cuda_bf16.h>
#include <math.h>
#include <stdint.h>

// ---------------- problem constants ----------------
#define B_ 2
#define T_ 4096
#define HID_ 2048
#define H_ 6
#define DKH 256
#define DVH 512
#define KEYD 1536
#define VALD 3072
#define ROWS_ (B_ * T_)          // 8192
#define DVS 64                   // dv slice per scan CTA
#define NSL 8                    // 512/64
#define TOKB 8                   // tokens staged per scan round
#define LOSCALE 2048.0f
#define INVLOSCALE (1.0f / 2048.0f)

// ---------------- scratch (device globals; no allocation allowed) ----------------
__device__ float g_xq[ROWS_ * KEYD];
__device__ float g_xk[ROWS_ * KEYD];
__device__ float g_xv[ROWS_ * VALD];
__device__ float g_gt[ROWS_ * VALD];
__device__ float g_qn[ROWS_ * KEYD];
__device__ float g_kn[ROWS_ * KEYD];
__device__ float g_vn[ROWS_ * VALD];
__device__ float g_od[ROWS_ * VALD];
__device__ float g_gd[ROWS_ * H_];
__device__ float g_bt[ROWS_ * H_];
__device__ float g_wat[H_ * HID_];
__device__ float g_wbt[H_ * HID_];
// fp16 split buffers (activation lo scaled by 2^11); weights hi-only
__device__ __half g_ah[ROWS_ * HID_];
__device__ __half g_al[ROWS_ * HID_];
__device__ __half g_yh[ROWS_ * VALD];
__device__ __half g_yl[ROWS_ * VALD];
__device__ __half g_wqkh[2 * KEYD * HID_];   // Wq rows then Wk rows, [N,K]
__device__ __half g_wvgh[2 * VALD * HID_];   // Wv rows then Wg rows
__device__ __half g_woh[HID_ * VALD];

// ---------------- packed f32x2 helpers ----------------
__device__ __forceinline__ unsigned long long pk2(float x, float y) {
    unsigned long long r;
    asm("mov.b64 %0, {%1, %2};" : "=l"(r) : "f"(x), "f"(y));
    return r;
}
__device__ __forceinline__ float2 up2(unsigned long long v) {
    float2 r;
    asm("mov.b64 {%0, %1}, %2;" : "=f"(r.x), "=f"(r.y) : "l"(v));
    return r;
}
__device__ __forceinline__ unsigned long long fma2u(unsigned long long a, unsigned long long b, unsigned long long c) {
    unsigned long long d;
    asm("fma.rn.f32x2 %0, %1, %2, %3;" : "=l"(d) : "l"(a), "l"(b), "l"(c));
    return d;
}
__device__ __forceinline__ unsigned long long mul2u(unsigned long long a, unsigned long long b) {
    unsigned long long d;
    asm("mul.rn.f32x2 %0, %1, %2;" : "=l"(d) : "l"(a), "l"(b));
    return d;
}

// ---------------- mma.sync / ldmatrix / cp.async helpers ----------------
__device__ __forceinline__ uint32_t smem_u32(const void* p) {
    uint32_t a;
    asm("{ .reg .u64 t; cvta.to.shared.u64 t, %1; cvt.u32.u64 %0, t; }" : "=r"(a) : "l"(p));
    return a;
}
__device__ __forceinline__ void ldm_x4(uint32_t* r, uint32_t addr) {
    asm volatile("ldmatrix.sync.aligned.m8n8.x4.shared.b16 {%0,%1,%2,%3}, [%4];"
                 : "=r"(r[0]), "=r"(r[1]), "=r"(r[2]), "=r"(r[3]) : "r"(addr));
}
// f16 inputs, f32 accumulate (main product)
__device__ __forceinline__ void mma_hf32(float* c, const uint32_t* a, const uint32_t* b) {
    asm volatile("mma.sync.aligned.m16n8k16.row.col.f32.f16.f16.f32 "
                 "{%0,%1,%2,%3}, {%4,%5,%6,%7}, {%8,%9}, {%0,%1,%2,%3};"
                 : "+f"(c[0]), "+f"(c[1]), "+f"(c[2]), "+f"(c[3])
                 : "r"(a[0]), "r"(a[1]), "r"(a[2]), "r"(a[3]), "r"(b[0]), "r"(b[1]));
}
// f16 inputs, f16 accumulate (correction product)
__device__ __forceinline__ void mma_hf16(uint32_t* c, const uint32_t* a, const uint32_t* b) {
    asm volatile("mma.sync.aligned.m16n8k16.row.col.f16.f16.f16.f16 "
                 "{%0,%1}, {%2,%3,%4,%5}, {%6,%7}, {%0,%1};"
                 : "+r"(c[0]), "+r"(c[1])
                 : "r"(a[0]), "r"(a[1]), "r"(a[2]), "r"(a[3]), "r"(b[0]), "r"(b[1]));
}
__device__ __forceinline__ void cp16(uint32_t sm, const void* gp) {
    asm volatile("cp.async.cg.shared.global [%0], [%1], 16;" :: "r"(sm), "l"(gp));
}
#define CP_COMMIT() asm volatile("cp.async.commit_group;" ::: "memory")
#define CP_WAIT0()  asm volatile("cp.async.wait_group 0;" ::: "memory")

// ---------------- fp16-split HMMA GEMM (2 products) ----------------
// C[M,N] = A[M,K] @ B^T; A row-major (hi + 2^11-scaled lo fp16), B [N,K] hi-only.
// C = Ah*Bh (f32 acc) + 2^-11 * (Al'*Bh) (f16 acc). Weight residual dropped
// (~2^-12 relative, random-walks over K -> ~1e-4 output error; budget 1e-3).
// CTA 128x128, 256 threads, warp tile 64x32, K-chunk 64, cp.async double buffer.
// SMEM rows padded to 72 halves (144B) -> conflict-free ldmatrix.
// Fused-output: columns [0,splitN) -> C0, [splitN,N) -> C1; both row-stride splitN.
#define GTILE 18432            // 128 rows * 144 B
#define GBUF  55296            // 3 tiles
#define GEMM_SMEM 110592       // 2 buffers

__global__ __launch_bounds__(256, 1)
void gemm_hx2(const __half* __restrict__ Ahi, const __half* __restrict__ Alo,
              const __half* __restrict__ Bhi,
              float* __restrict__ C0, float* __restrict__ C1,
              int splitN, int M, int N, int K) {
    extern __shared__ __align__(16) char smem[];
    const uint32_t sbase = smem_u32(smem);
    const int tid = threadIdx.x, lane = tid & 31, wid = tid >> 5;
    const int wm = wid & 1, wn = wid >> 1;      // 2 x 4 warp grid
    const int brow = blockIdx.y * 128, bcol = blockIdx.x * 128;

    const __half* srcs[3] = {Ahi, Alo, Bhi};
    const int row0[3] = {brow, brow, bcol};

    float accF[4][4][4];
    uint32_t accH[4][4][2];
#pragma unroll
    for (int i = 0; i < 4; i++)
#pragma unroll
        for (int j = 0; j < 4; j++) {
#pragma unroll
            for (int l = 0; l < 4; l++) accF[i][j][l] = 0.f;
            accH[i][j][0] = 0u; accH[i][j][1] = 0u;
        }

    const int r_ = tid >> 3, c8_ = (tid & 7) * 8;   // per-thread load coords

    // prologue: chunk 0 -> buf 0
#pragma unroll
    for (int ts = 0; ts < 3; ts++) {
        const __half* sp = srcs[ts] + (size_t)(row0[ts] + r_) * K + c8_;
        uint32_t tb = sbase + ts * GTILE + r_ * 144 + c8_ * 2;
#pragma unroll
        for (int i = 0; i < 4; i++)
            cp16(tb + i * 32 * 144, sp + (size_t)(i * 32) * K);
    }
    CP_COMMIT();
    CP_WAIT0();
    __syncthreads();

    const int numT = K >> 6;
    const uint32_t a_lane = (lane & 15) * 144 + (lane >> 4) * 16;
    // B x4: lanes 0-7 rows n0..n0+7 k0 | 8-15 same rows k1 | 16-23 rows +8 k0 | 24-31 k1
    const uint32_t b_lane4 = ((lane & 7) + (lane >> 4) * 8) * 144 + ((lane >> 3) & 1) * 16;

    for (int c = 0; c < numT; c++) {
        const int b = c & 1;
        if (c + 1 < numT) {
            const int kc = (c + 1) << 6, nb = b ^ 1;
#pragma unroll
            for (int ts = 0; ts < 3; ts++) {
                const __half* sp = srcs[ts] + (size_t)(row0[ts] + r_) * K + kc + c8_;
                uint32_t tb = sbase + nb * GBUF + ts * GTILE + r_ * 144 + c8_ * 2;
#pragma unroll
                for (int i = 0; i < 4; i++)
                    cp16(tb + i * 32 * 144, sp + (size_t)(i * 32) * K);
            }
            CP_COMMIT();
        }
        const uint32_t aH = sbase + b * GBUF + wm * 64 * 144;
        const uint32_t aL = aH + GTILE;
        const uint32_t bH = sbase + b * GBUF + 2 * GTILE + wn * 32 * 144;
#pragma unroll
        for (int ks = 0; ks < 4; ks++) {
            const uint32_t acol = ks * 32 + a_lane;
            const uint32_t bcol2 = ks * 32 + b_lane4;
            uint32_t fAH[4][4], fAL[4][4], fBH[4][2];
#pragma unroll
            for (int mt = 0; mt < 4; mt++) {
                ldm_x4(fAH[mt], aH + mt * 16 * 144 + acol);
                ldm_x4(fAL[mt], aL + mt * 16 * 144 + acol);
            }
#pragma unroll
            for (int p = 0; p < 2; p++) {
                uint32_t r4[4];
                ldm_x4(r4, bH + p * 16 * 144 + bcol2);
                fBH[2 * p][0] = r4[0]; fBH[2 * p][1] = r4[1];
                fBH[2 * p + 1][0] = r4[2]; fBH[2 * p + 1][1] = r4[3];
            }
#pragma unroll
            for (int mt = 0; mt < 4; mt++)
#pragma unroll
                for (int nt = 0; nt < 4; nt++) {
                    mma_hf32(accF[mt][nt], fAH[mt], fBH[nt]);
                    mma_hf16(accH[mt][nt], fAL[mt], fBH[nt]);
                }
        }
        CP_WAIT0();
        __syncthreads();
    }

    // epilogue: merge f32 main + f16 correction, route to C0/C1
    float* Cp;
    int ccol0;
    if (bcol < splitN) { Cp = C0; ccol0 = bcol; }
    else               { Cp = C1; ccol0 = bcol - splitN; }
    const int r0 = lane >> 2, cc = (lane & 3) * 2;
#pragma unroll
    for (int mt = 0; mt < 4; mt++)
#pragma unroll
        for (int nt = 0; nt < 4; nt++) {
            float2 lo01 = __half22float2(*(__half2*)&accH[mt][nt][0]);
            float2 lo23 = __half22float2(*(__half2*)&accH[mt][nt][1]);
            size_t base = (size_t)(brow + wm * 64 + mt * 16 + r0) * splitN + ccol0 + wn * 32 + nt * 8 + cc;
            *(float2*)&Cp[base] = make_float2(accF[mt][nt][0] + lo01.x * INVLOSCALE,
                                              accF[mt][nt][1] + lo01.y * INVLOSCALE);
            *(float2*)&Cp[base + 8 * (size_t)splitN] = make_float2(accF[mt][nt][2] + lo23.x * INVLOSCALE,
                                                                   accF[mt][nt][3] + lo23.y * INVLOSCALE);
        }
}

// ---------------- fp32 -> fp16 hi/lo split (lo scaled by 2^11) ----------------
__global__ void split4(const float* __restrict__ x, __half* __restrict__ xh,
                       __half* __restrict__ xl) {
    int i4 = blockIdx.x * 256 + threadIdx.x;
    float4 v = ((const float4*)x)[i4];
    __half h0 = __float2half_rn(v.x), h1 = __float2half_rn(v.y);
    __half h2 = __float2half_rn(v.z), h3 = __float2half_rn(v.w);
    __half l0 = __float2half_rn((v.x - __half2float(h0)) * LOSCALE);
    __half l1 = __float2half_rn((v.y - __half2float(h1)) * LOSCALE);
    __half l2 = __float2half_rn((v.z - __half2float(h2)) * LOSCALE);
    __half l3 = __float2half_rn((v.w - __half2float(h3)) * LOSCALE);
    __half2* hp = (__half2*)(xh + (size_t)i4 * 4);
    __half2* lp = (__half2*)(xl + (size_t)i4 * 4);
    hp[0] = __halves2half2(h0, h1); hp[1] = __halves2half2(h2, h3);
    lp[0] = __halves2half2(l0, l1); lp[1] = __halves2half2(l2, l3);
}

// ---------------- weight transpose: W[K,N] -> Wh [N,K] fp16 (hi only) ----------------
__global__ void tsplit1(const float* __restrict__ W, __half* __restrict__ Wh, int K, int N) {
    __shared__ float tile[32][33];
    int n0 = blockIdx.x * 32, k0 = blockIdx.y * 32;
    int tx = threadIdx.x & 31, ty = threadIdx.x >> 5;   // 32x8
#pragma unroll
    for (int i = 0; i < 4; i++) {
        int k = k0 + ty + i * 8;
        tile[ty + i * 8][tx] = W[(size_t)k * N + n0 + tx];
    }
    __syncthreads();
#pragma unroll
    for (int i = 0; i < 4; i++) {
        int n = n0 + ty + i * 8;
        Wh[(size_t)n * K + k0 + tx] = __float2half_rn(tile[tx][ty + i * 8]);
    }
}

// ---------------- causal depthwise conv (K=4) + SiLU ----------------
__global__ void conv_silu_k(const float* __restrict__ x, const float* __restrict__ w,
                            float* __restrict__ y, int D) {
    int idx = blockIdx.x * 256 + threadIdx.x;
    int d = idx % D;
    int t = (idx / D) & (T_ - 1);
    float4 wv = *(const float4*)(w + d * 4);
    float acc = x[idx] * wv.w;
    if (t >= 1) acc += x[idx - D] * wv.z;
    if (t >= 2) acc += x[idx - 2 * D] * wv.y;
    if (t >= 3) acc += x[idx - 3 * D] * wv.x;
    y[idx] = acc / (1.f + expf(-acc));
}

// ---------------- per-(b,t,h) L2 norm over 256, in place, times scale ----------------
__global__ void l2norm_k(float* __restrict__ x, float scale) {
    int gw = (blockIdx.x * 256 + threadIdx.x) >> 5;
    int lane = threadIdx.x & 31;
    float* row = x + (size_t)gw * DKH;
    float4 v0 = *(const float4*)(row + lane * 8);
    float4 v1 = *(const float4*)(row + lane * 8 + 4);
    float ss = v0.x * v0.x + v0.y * v0.y + v0.z * v0.z + v0.w * v0.w +
               v1.x * v1.x + v1.y * v1.y + v1.z * v1.z + v1.w * v1.w;
#pragma unroll
    for (int o = 16; o; o >>= 1) ss += __shfl_xor_sync(0xffffffffu, ss, o);
    float r = rsqrtf(ss) * scale;
    v0.x *= r; v0.y *= r; v0.z *= r; v0.w *= r;
    v1.x *= r; v1.y *= r; v1.z *= r; v1.w *= r;
    *(float4*)(row + lane * 8) = v0;
    *(float4*)(row + lane * 8 + 4) = v1;
}

// ---------------- transpose Wa/Wb (2048x6 -> 6x2048) ----------------
__global__ void transpose6(const float* __restrict__ Wa, const float* __restrict__ Wb,
                           float* __restrict__ WaT, float* __restrict__ WbT) {
    int i = blockIdx.x * 256 + threadIdx.x;
    int c = i / H_, h = i % H_;
    WaT[h * HID_ + c] = Wa[i];
    WbT[h * HID_ + c] = Wb[i];
}

// ---------------- beta / decay projection ----------------
__global__ void proj_ab(const float* __restrict__ hid, const float* __restrict__ WaT,
                        const float* __restrict__ WbT, const float* __restrict__ A_log,
                        const float* __restrict__ dt_bias,
                        float* __restrict__ gdec, float* __restrict__ beta) {
    int gw = (blockIdx.x * 256 + threadIdx.x) >> 5;
    int lane = threadIdx.x & 31;
    const float* hr = hid + (size_t)gw * HID_;
    float da0 = 0, da1 = 0, da2 = 0, da3 = 0, da4 = 0, da5 = 0;
    float db0 = 0, db1 = 0, db2 = 0, db3 = 0, db4 = 0, db5 = 0;
    for (int c = lane; c < HID_; c += 32) {
        float hv = hr[c];
        da0 += hv * WaT[0 * HID_ + c]; db0 += hv * WbT[0 * HID_ + c];
        da1 += hv * WaT[1 * HID_ + c]; db1 += hv * WbT[1 * HID_ + c];
        da2 += hv * WaT[2 * HID_ + c]; db2 += hv * WbT[2 * HID_ + c];
        da3 += hv * WaT[3 * HID_ + c]; db3 += hv * WbT[3 * HID_ + c];
        da4 += hv * WaT[4 * HID_ + c]; db4 += hv * WbT[4 * HID_ + c];
        da5 += hv * WaT[5 * HID_ + c]; db5 += hv * WbT[5 * HID_ + c];
    }
#pragma unroll
    for (int o = 16; o; o >>= 1) {
        da0 += __shfl_xor_sync(~0u, da0, o); db0 += __shfl_xor_sync(~0u, db0, o);
        da1 += __shfl_xor_sync(~0u, da1, o); db1 += __shfl_xor_sync(~0u, db1, o);
        da2 += __shfl_xor_sync(~0u, da2, o); db2 += __shfl_xor_sync(~0u, db2, o);
        da3 += __shfl_xor_sync(~0u, da3, o); db3 += __shfl_xor_sync(~0u, db3, o);
        da4 += __shfl_xor_sync(~0u, da4, o); db4 += __shfl_xor_sync(~0u, db4, o);
        da5 += __shfl_xor_sync(~0u, da5, o); db5 += __shfl_xor_sync(~0u, db5, o);
    }
    if (lane == 0) {
        float da[6] = {da0, da1, da2, da3, da4, da5};
        float db[6] = {db0, db1, db2, db3, db4, db5};
#pragma unroll
        for (int h = 0; h < 6; h++) {
            float x = da[h] + dt_bias[h];
            float sp = (x > 20.f) ? x : log1pf(expf(x));
            gdec[gw * H_ + h] = -expf(A_log[h]) * sp;
            beta[gw * H_ + h] = 1.f / (1.f + expf(-db[h]));
        }
    }
}

// ---------------- gated delta rule scan (R4 known-good version) ----------------
__global__ __launch_bounds__(256, 1)
void delta_scan(const float* __restrict__ q, const float* __restrict__ k,
                const float* __restrict__ v, const float* __restrict__ g,
                const float* __restrict__ beta, float* __restrict__ o) {
    __shared__ __align__(16) float ks[TOKB][272];
    __shared__ __align__(16) float qs[TOKB][272];
    __shared__ float vs[TOKB][DVS];
    __shared__ float egs[TOKB];
    __shared__ float bts[TOKB];

    const int bi = blockIdx.x;
    const int s = bi & 7;
    const int h = (bi >> 3) % H_;
    const int b = bi / (H_ * NSL);
    const int tid = threadIdx.x;
    const int vl = tid >> 2, kseg = tid & 3;
    const int sidx = (tid >> 6) * 68 + (tid & 63);

    unsigned long long S[32];
#pragma unroll
    for (int m = 0; m < 32; m++) S[m] = 0ull;

    for (int t0 = 0; t0 < T_; t0 += TOKB) {
#pragma unroll
        for (int tt = 0; tt < TOKB; tt++) {
            size_t base = ((size_t)(b * T_ + t0 + tt) * H_ + h) * DKH;
            ks[tt][sidx] = k[base + tid];
            qs[tt][sidx] = q[base + tid];
        }
#pragma unroll
        for (int i = 0; i < 2; i++) {
            int ee = i * 256 + tid;
            int tt = ee >> 6, vle = ee & 63;
            vs[tt][vle] = v[((size_t)(b * T_ + t0 + tt) * H_ + h) * DVH + s * DVS + vle];
        }
        if (tid < TOKB) {
            size_t gi = (size_t)(b * T_ + t0 + tid) * H_ + h;
            egs[tid] = expf(g[gi]);
            bts[tid] = beta[gi];
        }
        __syncthreads();

#pragma unroll 1
        for (int tt = 0; tt < TOKB; tt++) {
            float eg = egs[tt], bt = bts[tt], vv = vs[tt][vl];
            const float4* kp = (const float4*)&ks[tt][kseg * 68];
            const float4* qp = (const float4*)&qs[tt][kseg * 68];

            unsigned long long a0 = 0ull, a1 = 0ull;
#pragma unroll
            for (int m4 = 0; m4 < 16; m4++) {
                float4 k4 = kp[m4];
                a0 = fma2u(pk2(k4.x, k4.y), S[2 * m4], a0);
                a1 = fma2u(pk2(k4.z, k4.w), S[2 * m4 + 1], a1);
            }
            float2 f0 = up2(a0), f1 = up2(a1);
            float pred = f0.x + f0.y + f1.x + f1.y;
            pred += __shfl_xor_sync(0xffffffffu, pred, 1);
            pred += __shfl_xor_sync(0xffffffffu, pred, 2);
            pred *= eg;
            float delta = (vv - pred) * bt;

            unsigned long long eg2 = pk2(eg, eg), d2 = pk2(delta, delta);
            unsigned long long o0 = 0ull, o1 = 0ull;
#pragma unroll
            for (int m4 = 0; m4 < 16; m4++) {
                float4 k4 = kp[m4];
                float4 q4 = qp[m4];
                unsigned long long s0 = fma2u(pk2(k4.x, k4.y), d2, mul2u(eg2, S[2 * m4]));
                unsigned long long s1 = fma2u(pk2(k4.z, k4.w), d2, mul2u(eg2, S[2 * m4 + 1]));
                S[2 * m4] = s0;
                S[2 * m4 + 1] = s1;
                o0 = fma2u(pk2(q4.x, q4.y), s0, o0);
                o1 = fma2u(pk2(q4.z, q4.w), s1, o1);
            }
            float2 g0 = up2(o0), g1 = up2(o1);
            float ov = g0.x + g0.y + g1.x + g1.y;
            ov += __shfl_xor_sync(0xffffffffu, ov, 1);
            ov += __shfl_xor_sync(0xffffffffu, ov, 2);
            if (kseg == 0)
                o[((size_t)(b * T_ + t0 + tt) * H_ + h) * DVH + s * DVS + vl] = ov;
        }
        __syncthreads();
    }
}

// ---------------- RMSNorm * weight * silu(gate) -> fp16 hi/lo split ----------------
__global__ void norm_gate(const float* __restrict__ o, const float* __restrict__ gate,
                          const float* __restrict__ nw,
                          __half* __restrict__ yh, __half* __restrict__ yl) {
    int gw = (blockIdx.x * 256 + threadIdx.x) >> 5;
    int lane = threadIdx.x & 31;
    size_t base = (size_t)gw * DVH;
    float4 v[4];
    float ss = 0.f;
#pragma unroll
    for (int i = 0; i < 4; i++) {
        v[i] = *(const float4*)(o + base + (lane + i * 32) * 4);
        ss += v[i].x * v[i].x + v[i].y * v[i].y + v[i].z * v[i].z + v[i].w * v[i].w;
    }
#pragma unroll
    for (int off = 16; off; off >>= 1) ss += __shfl_xor_sync(0xffffffffu, ss, off);
    float r = rsqrtf(ss * (1.f / 512.f) + 1e-5f);
#pragma unroll
    for (int i = 0; i < 4; i++) {
        int d4 = (lane + i * 32) * 4;
        float4 gt = *(const float4*)(gate + base + d4);
        float4 w = *(const float4*)(nw + d4);
        float o0 = v[i].x * r * w.x * (gt.x / (1.f + expf(-gt.x)));
        float o1 = v[i].y * r * w.y * (gt.y / (1.f + expf(-gt.y)));
        float o2 = v[i].z * r * w.z * (gt.z / (1.f + expf(-gt.z)));
        float o3 = v[i].w * r * w.w * (gt.w / (1.f + expf(-gt.w)));
        __half h0 = __float2half_rn(o0), h1 = __float2half_rn(o1);
        __half h2 = __float2half_rn(o2), h3 = __float2half_rn(o3);
        __half2* hp = (__half2*)(yh + base + d4);
        __half2* lp = (__half2*)(yl + base + d4);
        hp[0] = __halves2half2(h0, h1);
        hp[1] = __halves2half2(h2, h3);
        lp[0] = __halves2half2(__float2half_rn((o0 - __half2float(h0)) * LOSCALE),
                               __float2half_rn((o1 - __half2float(h1)) * LOSCALE));
        lp[1] = __halves2half2(__float2half_rn((o2 - __half2float(h2)) * LOSCALE),
                               __float2half_rn((o3 - __half2float(h3)) * LOSCALE));
    }
}

// ---------------- launch ----------------
extern "C" void kernel_launch(void* const* d_in, const int* in_sizes, int n_in,
                              void* d_out, int out_size) {
    const float* hid  = (const float*)d_in[0];
    const float* Wq   = (const float*)d_in[1];
    const float* Wk   = (const float*)d_in[2];
    const float* Wv   = (const float*)d_in[3];
    const float* Wa   = (const float*)d_in[4];
    const float* Wb   = (const float*)d_in[5];
    const float* Wg   = (const float*)d_in[6];
    const float* Wo   = (const float*)d_in[7];
    const float* cwq  = (const float*)d_in[8];
    const float* cwk  = (const float*)d_in[9];
    const float* cwv  = (const float*)d_in[10];
    const float* Alog = (const float*)d_in[11];
    const float* dtb  = (const float*)d_in[12];
    const float* nw   = (const float*)d_in[13];

    float *xq, *xk, *xv, *gt, *qn, *kn, *vn, *od, *gd, *bt, *wat, *wbt;
    __half *ah, *al, *yh, *yl, *wqkh, *wvgh, *woh;
    cudaGetSymbolAddress((void**)&xq, g_xq);
    cudaGetSymbolAddress((void**)&xk, g_xk);
    cudaGetSymbolAddress((void**)&xv, g_xv);
    cudaGetSymbolAddress((void**)&gt, g_gt);
    cudaGetSymbolAddress((void**)&qn, g_qn);
    cudaGetSymbolAddress((void**)&kn, g_kn);
    cudaGetSymbolAddress((void**)&vn, g_vn);
    cudaGetSymbolAddress((void**)&od, g_od);
    cudaGetSymbolAddress((void**)&gd, g_gd);
    cudaGetSymbolAddress((void**)&bt, g_bt);
    cudaGetSymbolAddress((void**)&wat, g_wat);
    cudaGetSymbolAddress((void**)&wbt, g_wbt);
    cudaGetSymbolAddress((void**)&ah, g_ah);
    cudaGetSymbolAddress((void**)&al, g_al);
    cudaGetSymbolAddress((void**)&yh, g_yh);
    cudaGetSymbolAddress((void**)&yl, g_yl);
    cudaGetSymbolAddress((void**)&wqkh, g_wqkh);
    cudaGetSymbolAddress((void**)&wvgh, g_wvgh);
    cudaGetSymbolAddress((void**)&woh, g_woh);

    cudaFuncSetAttribute(gemm_hx2, cudaFuncAttributeMaxDynamicSharedMemorySize, GEMM_SMEM);

    // fp16 splits: activations (hi+lo) + weights (hi only, transposed to [N,K])
    split4<<<(ROWS_ * HID_ / 4) / 256, 256>>>(hid, ah, al);
    tsplit1<<<dim3(KEYD / 32, HID_ / 32), 256>>>(Wq, wqkh, HID_, KEYD);
    tsplit1<<<dim3(KEYD / 32, HID_ / 32), 256>>>(Wk, wqkh + (size_t)KEYD * HID_, HID_, KEYD);
    tsplit1<<<dim3(VALD / 32, HID_ / 32), 256>>>(Wv, wvgh, HID_, VALD);
    tsplit1<<<dim3(VALD / 32, HID_ / 32), 256>>>(Wg, wvgh + (size_t)VALD * HID_, HID_, VALD);
    tsplit1<<<dim3(HID_ / 32, VALD / 32), 256>>>(Wo, woh, VALD, HID_);

    // fused tensor-core projections: QK (N=3072), VG (N=6144)
    gemm_hx2<<<dim3(2 * KEYD / 128, ROWS_ / 128), 256, GEMM_SMEM>>>(ah, al, wqkh, xq, xk, KEYD, ROWS_, 2 * KEYD, HID_);
    gemm_hx2<<<dim3(2 * VALD / 128, ROWS_ / 128), 256, GEMM_SMEM>>>(ah, al, wvgh, xv, gt, VALD, ROWS_, 2 * VALD, HID_);

    // beta / decay
    transpose6<<<(H_ * HID_) / 256, 256>>>(Wa, Wb, wat, wbt);
    proj_ab<<<(ROWS_ * 32) / 256, 256>>>(hid, wat, wbt, Alog, dtb, gd, bt);

    // conv + silu
    conv_silu_k<<<(ROWS_ * KEYD) / 256, 256>>>(xq, cwq, qn, KEYD);
    conv_silu_k<<<(ROWS_ * KEYD) / 256, 256>>>(xk, cwk, kn, KEYD);
    conv_silu_k<<<(ROWS_ * VALD) / 256, 256>>>(xv, cwv, vn, VALD);

    // l2 norms (q also scaled by dk^-0.5 = 1/16)
    l2norm_k<<<(ROWS_ * H_ * 32) / 256, 256>>>(qn, 0.0625f);
    l2norm_k<<<(ROWS_ * H_ * 32) / 256, 256>>>(kn, 1.0f);

    // sequential gated delta rule
    delta_scan<<<B_ * H_ * NSL, 256>>>(qn, kn, vn, gd, bt, od);

    // rmsnorm * weight * silu(gate) -> fp16 hi/lo
    norm_gate<<<(ROWS_ * H_ * 32) / 256, 256>>>(od, gt, nw, yh, yl);

    // output projection -> d_out (unfused: splitN = N)
    gemm_hx2<<<dim3(HID_ / 128, ROWS_ / 128), 256, GEMM_SMEM>>>(yh, yl, woh, (float*)d_out, (float*)d_out, HID_, ROWS_, HID_, VALD);
}

// round 9
// speedup vs baseline: 1.3944x; 1.1530x over previous
#include <cuda_runtime.h>
#include <cuda_fp16.h>
#include <math.h>
#include <stdint.h>

// ---------------- problem constants ----------------
#define B_ 2
#define T_ 4096
#define HID_ 2048
#define H_ 6
#define DKH 256
#define DVH 512
#define KEYD 1536
#define VALD 3072
#define ROWS_ (B_ * T_)          // 8192
#define DVS 64                   // dv slice per scan CTA
#define NSL 8                    // 512/64
#define TOKB 8                   // tokens staged per scan round
#define LOSCALE 2048.0f
#define INVLOSCALE (1.0f / 2048.0f)
#define SCAN_CTAS (B_ * H_ * NSL)   // 96

// ---------------- scratch (device globals; no allocation allowed) ----------------
__device__ float g_xq[ROWS_ * KEYD];
__device__ float g_xk[ROWS_ * KEYD];
__device__ float g_xv[ROWS_ * VALD];
__device__ float g_gt[ROWS_ * VALD];
__device__ float g_qn[ROWS_ * KEYD];
__device__ float g_kn[ROWS_ * KEYD];
__device__ float g_vn[ROWS_ * VALD];
__device__ float g_od[ROWS_ * VALD];
__device__ float g_gd[ROWS_ * H_];
__device__ float g_bt[ROWS_ * H_];
__device__ float g_wat[H_ * HID_];
__device__ float g_wbt[H_ * HID_];
// fp16 buffers (activation lo scaled by 2^11); weights hi-only
__device__ __half g_ah[ROWS_ * HID_];
__device__ __half g_al[ROWS_ * HID_];
__device__ __half g_yh[ROWS_ * VALD];
__device__ __half g_yl[ROWS_ * VALD];
__device__ __half g_wqkvh[(2 * KEYD + VALD) * HID_];  // Wq | Wk | Wv rows, [N,K]
__device__ __half g_wgh[VALD * HID_];
__device__ __half g_woh[HID_ * VALD];

// ---------------- packed f32x2 helpers ----------------
__device__ __forceinline__ unsigned long long pk2(float x, float y) {
    unsigned long long r;
    asm("mov.b64 %0, {%1, %2};" : "=l"(r) : "f"(x), "f"(y));
    return r;
}
__device__ __forceinline__ float2 up2(unsigned long long v) {
    float2 r;
    asm("mov.b64 {%0, %1}, %2;" : "=f"(r.x), "=f"(r.y) : "l"(v));
    return r;
}
__device__ __forceinline__ unsigned long long fma2u(unsigned long long a, unsigned long long b, unsigned long long c) {
    unsigned long long d;
    asm("fma.rn.f32x2 %0, %1, %2, %3;" : "=l"(d) : "l"(a), "l"(b), "l"(c));
    return d;
}
__device__ __forceinline__ unsigned long long mul2u(unsigned long long a, unsigned long long b) {
    unsigned long long d;
    asm("mul.rn.f32x2 %0, %1, %2;" : "=l"(d) : "l"(a), "l"(b));
    return d;
}

// ---------------- mma.sync / ldmatrix / cp.async helpers ----------------
__device__ __forceinline__ uint32_t smem_u32(const void* p) {
    uint32_t a;
    asm("{ .reg .u64 t; cvta.to.shared.u64 t, %1; cvt.u32.u64 %0, t; }" : "=r"(a) : "l"(p));
    return a;
}
__device__ __forceinline__ void ldm_x4(uint32_t* r, uint32_t addr) {
    asm volatile("ldmatrix.sync.aligned.m8n8.x4.shared.b16 {%0,%1,%2,%3}, [%4];"
                 : "=r"(r[0]), "=r"(r[1]), "=r"(r[2]), "=r"(r[3]) : "r"(addr));
}
__device__ __forceinline__ void mma_hf32(float* c, const uint32_t* a, const uint32_t* b) {
    asm volatile("mma.sync.aligned.m16n8k16.row.col.f32.f16.f16.f32 "
                 "{%0,%1,%2,%3}, {%4,%5,%6,%7}, {%8,%9}, {%0,%1,%2,%3};"
                 : "+f"(c[0]), "+f"(c[1]), "+f"(c[2]), "+f"(c[3])
                 : "r"(a[0]), "r"(a[1]), "r"(a[2]), "r"(a[3]), "r"(b[0]), "r"(b[1]));
}
__device__ __forceinline__ void mma_hf16(uint32_t* c, const uint32_t* a, const uint32_t* b) {
    asm volatile("mma.sync.aligned.m16n8k16.row.col.f16.f16.f16.f16 "
                 "{%0,%1}, {%2,%3,%4,%5}, {%6,%7}, {%0,%1};"
                 : "+r"(c[0]), "+r"(c[1])
                 : "r"(a[0]), "r"(a[1]), "r"(a[2]), "r"(a[3]), "r"(b[0]), "r"(b[1]));
}
__device__ __forceinline__ void cp16(uint32_t sm, const void* gp) {
    asm volatile("cp.async.cg.shared.global [%0], [%1], 16;" :: "r"(sm), "l"(gp));
}
#define CP_COMMIT() asm volatile("cp.async.commit_group;" ::: "memory")
#define CP_WAIT0()  asm volatile("cp.async.wait_group 0;" ::: "memory")

// ---------------- fp16-split HMMA GEMM tile (2 products), device body ----------------
// C = Ah*Bh (f32 acc) + 2^-11 * (Al'*Bh) (f16 acc); B [N,K] hi-only.
// 3-way column routing: [0,split1)->C0/str0, [split1,split2)->C1/str1, rest->C2/str2.
#define GTILE 18432            // 128 rows * 144 B
#define GBUF  55296            // 3 tiles
#define GEMM_SMEM 110592       // 2 buffers

__device__ __forceinline__ void gemm_tile(
    const __half* __restrict__ Ahi, const __half* __restrict__ Alo,
    const __half* __restrict__ Bhi,
    float* __restrict__ C0, float* __restrict__ C1, float* __restrict__ C2,
    int split1, int split2, int str0, int str1, int str2,
    int K, int bx, int by, char* smem) {
    const uint32_t sbase = smem_u32(smem);
    const int tid = threadIdx.x, lane = tid & 31, wid = tid >> 5;
    const int wm = wid & 1, wn = wid >> 1;      // 2 x 4 warp grid
    const int brow = by * 128, bcol = bx * 128;

    const __half* srcs[3] = {Ahi, Alo, Bhi};
    const int row0[3] = {brow, brow, bcol};

    float accF[4][4][4];
    uint32_t accH[4][4][2];
#pragma unroll
    for (int i = 0; i < 4; i++)
#pragma unroll
        for (int j = 0; j < 4; j++) {
#pragma unroll
            for (int l = 0; l < 4; l++) accF[i][j][l] = 0.f;
            accH[i][j][0] = 0u; accH[i][j][1] = 0u;
        }

    const int r_ = tid >> 3, c8_ = (tid & 7) * 8;

    // prologue: chunk 0 -> buf 0
#pragma unroll
    for (int ts = 0; ts < 3; ts++) {
        const __half* sp = srcs[ts] + (size_t)(row0[ts] + r_) * K + c8_;
        uint32_t tb = sbase + ts * GTILE + r_ * 144 + c8_ * 2;
#pragma unroll
        for (int i = 0; i < 4; i++)
            cp16(tb + i * 32 * 144, sp + (size_t)(i * 32) * K);
    }
    CP_COMMIT();
    CP_WAIT0();
    __syncthreads();

    const int numT = K >> 6;
    const uint32_t a_lane = (lane & 15) * 144 + (lane >> 4) * 16;
    const uint32_t b_lane4 = ((lane & 7) + (lane >> 4) * 8) * 144 + ((lane >> 3) & 1) * 16;

    for (int c = 0; c < numT; c++) {
        const int b = c & 1;
        if (c + 1 < numT) {
            const int kc = (c + 1) << 6, nb = b ^ 1;
#pragma unroll
            for (int ts = 0; ts < 3; ts++) {
                const __half* sp = srcs[ts] + (size_t)(row0[ts] + r_) * K + kc + c8_;
                uint32_t tb = sbase + nb * GBUF + ts * GTILE + r_ * 144 + c8_ * 2;
#pragma unroll
                for (int i = 0; i < 4; i++)
                    cp16(tb + i * 32 * 144, sp + (size_t)(i * 32) * K);
            }
            CP_COMMIT();
        }
        const uint32_t aH = sbase + b * GBUF + wm * 64 * 144;
        const uint32_t aL = aH + GTILE;
        const uint32_t bH = sbase + b * GBUF + 2 * GTILE + wn * 32 * 144;
#pragma unroll
        for (int ks = 0; ks < 4; ks++) {
            const uint32_t acol = ks * 32 + a_lane;
            const uint32_t bcol2 = ks * 32 + b_lane4;
            uint32_t fAH[4][4], fAL[4][4], fBH[4][2];
#pragma unroll
            for (int mt = 0; mt < 4; mt++) {
                ldm_x4(fAH[mt], aH + mt * 16 * 144 + acol);
                ldm_x4(fAL[mt], aL + mt * 16 * 144 + acol);
            }
#pragma unroll
            for (int p = 0; p < 2; p++) {
                uint32_t r4[4];
                ldm_x4(r4, bH + p * 16 * 144 + bcol2);
                fBH[2 * p][0] = r4[0]; fBH[2 * p][1] = r4[1];
                fBH[2 * p + 1][0] = r4[2]; fBH[2 * p + 1][1] = r4[3];
            }
#pragma unroll
            for (int mt = 0; mt < 4; mt++)
#pragma unroll
                for (int nt = 0; nt < 4; nt++) {
                    mma_hf32(accF[mt][nt], fAH[mt], fBH[nt]);
                    mma_hf16(accH[mt][nt], fAL[mt], fBH[nt]);
                }
        }
        CP_WAIT0();
        __syncthreads();
    }

    // epilogue: merge + 3-way route
    float* Cp; int ccol0, strN;
    if (bcol < split1)      { Cp = C0; ccol0 = bcol;          strN = str0; }
    else if (bcol < split2) { Cp = C1; ccol0 = bcol - split1; strN = str1; }
    else                    { Cp = C2; ccol0 = bcol - split2; strN = str2; }
    const int r0 = lane >> 2, cc = (lane & 3) * 2;
#pragma unroll
    for (int mt = 0; mt < 4; mt++)
#pragma unroll
        for (int nt = 0; nt < 4; nt++) {
            float2 lo01 = __half22float2(*(__half2*)&accH[mt][nt][0]);
            float2 lo23 = __half22float2(*(__half2*)&accH[mt][nt][1]);
            size_t base = (size_t)(brow + wm * 64 + mt * 16 + r0) * strN + ccol0 + wn * 32 + nt * 8 + cc;
            *(float2*)&Cp[base] = make_float2(accF[mt][nt][0] + lo01.x * INVLOSCALE,
                                              accF[mt][nt][1] + lo01.y * INVLOSCALE);
            *(float2*)&Cp[base + 8 * (size_t)strN] = make_float2(accF[mt][nt][2] + lo23.x * INVLOSCALE,
                                                                 accF[mt][nt][3] + lo23.y * INVLOSCALE);
        }
}

__global__ __launch_bounds__(256, 1)
void gemm_hx2(const __half* __restrict__ Ahi, const __half* __restrict__ Alo,
              const __half* __restrict__ Bhi,
              float* C0, float* C1, float* C2,
              int split1, int split2, int str0, int str1, int str2, int K) {
    extern __shared__ __align__(16) char smem[];
    gemm_tile(Ahi, Alo, Bhi, C0, C1, C2, split1, split2, str0, str1, str2,
              K, blockIdx.x, blockIdx.y, smem);
}

// ---------------- gated delta rule scan, device body ----------------
__device__ __forceinline__ void scan_body(
    const float* __restrict__ q, const float* __restrict__ k,
    const float* __restrict__ v, const float* __restrict__ g,
    const float* __restrict__ beta, float* __restrict__ o,
    int bi, char* smemc) {
    float (*ks)[272] = (float(*)[272])(smemc);
    float (*qs)[272] = (float(*)[272])(smemc + 8704);
    float (*vs)[DVS] = (float(*)[DVS])(smemc + 17408);
    float* egs = (float*)(smemc + 19456);
    float* bts = (float*)(smemc + 19488);

    const int s = bi & 7;
    const int h = (bi >> 3) % H_;
    const int b = bi / (H_ * NSL);
    const int tid = threadIdx.x;
    const int vl = tid >> 2, kseg = tid & 3;
    const int sidx = (tid >> 6) * 68 + (tid & 63);

    unsigned long long S[32];
#pragma unroll
    for (int m = 0; m < 32; m++) S[m] = 0ull;

    for (int t0 = 0; t0 < T_; t0 += TOKB) {
#pragma unroll
        for (int tt = 0; tt < TOKB; tt++) {
            size_t base = ((size_t)(b * T_ + t0 + tt) * H_ + h) * DKH;
            ks[tt][sidx] = k[base + tid];
            qs[tt][sidx] = q[base + tid];
        }
#pragma unroll
        for (int i = 0; i < 2; i++) {
            int ee = i * 256 + tid;
            int tt = ee >> 6, vle = ee & 63;
            vs[tt][vle] = v[((size_t)(b * T_ + t0 + tt) * H_ + h) * DVH + s * DVS + vle];
        }
        if (tid < TOKB) {
            size_t gi = (size_t)(b * T_ + t0 + tid) * H_ + h;
            egs[tid] = expf(g[gi]);
            bts[tid] = beta[gi];
        }
        __syncthreads();

#pragma unroll 1
        for (int tt = 0; tt < TOKB; tt++) {
            float eg = egs[tt], bt = bts[tt], vv = vs[tt][vl];
            const float4* kp = (const float4*)&ks[tt][kseg * 68];
            const float4* qp = (const float4*)&qs[tt][kseg * 68];

            unsigned long long a0 = 0ull, a1 = 0ull;
#pragma unroll
            for (int m4 = 0; m4 < 16; m4++) {
                float4 k4 = kp[m4];
                a0 = fma2u(pk2(k4.x, k4.y), S[2 * m4], a0);
                a1 = fma2u(pk2(k4.z, k4.w), S[2 * m4 + 1], a1);
            }
            float2 f0 = up2(a0), f1 = up2(a1);
            float pred = f0.x + f0.y + f1.x + f1.y;
            pred += __shfl_xor_sync(0xffffffffu, pred, 1);
            pred += __shfl_xor_sync(0xffffffffu, pred, 2);
            pred *= eg;
            float delta = (vv - pred) * bt;

            unsigned long long eg2 = pk2(eg, eg), d2 = pk2(delta, delta);
            unsigned long long o0 = 0ull, o1 = 0ull;
#pragma unroll
            for (int m4 = 0; m4 < 16; m4++) {
                float4 k4 = kp[m4];
                float4 q4 = qp[m4];
                unsigned long long s0 = fma2u(pk2(k4.x, k4.y), d2, mul2u(eg2, S[2 * m4]));
                unsigned long long s1 = fma2u(pk2(k4.z, k4.w), d2, mul2u(eg2, S[2 * m4 + 1]));
                S[2 * m4] = s0;
                S[2 * m4 + 1] = s1;
                o0 = fma2u(pk2(q4.x, q4.y), s0, o0);
                o1 = fma2u(pk2(q4.z, q4.w), s1, o1);
            }
            float2 g0 = up2(o0), g1 = up2(o1);
            float ov = g0.x + g0.y + g1.x + g1.y;
            ov += __shfl_xor_sync(0xffffffffu, ov, 1);
            ov += __shfl_xor_sync(0xffffffffu, ov, 2);
            if (kseg == 0)
                o[((size_t)(b * T_ + t0 + tt) * H_ + h) * DVH + s * DVS + vl] = ov;
        }
        __syncthreads();
    }
}

// ---------------- fat kernel: scan (96 CTAs) + gate GEMM (1536 CTAs) ----------------
// Scan blocks 0..95 land on distinct SMs in wave 1; short GEMM CTAs backfill the
// remaining ~52 SMs and take the whole chip once the scan drains.
__global__ __launch_bounds__(256, 1)
void scan_gemm(const float* __restrict__ qn, const float* __restrict__ kn,
               const float* __restrict__ vn, const float* __restrict__ gd,
               const float* __restrict__ bt, float* __restrict__ od,
               const __half* __restrict__ ah, const __half* __restrict__ al,
               const __half* __restrict__ wgh, float* __restrict__ gt) {
    extern __shared__ __align__(16) char smem[];
    if (blockIdx.x < SCAN_CTAS) {
        scan_body(qn, kn, vn, gd, bt, od, blockIdx.x, smem);
    } else {
        int gi = blockIdx.x - SCAN_CTAS;
        gemm_tile(ah, al, wgh, gt, gt, gt, VALD, VALD, VALD, VALD, VALD,
                  HID_, gi % (VALD / 128), gi / (VALD / 128), smem);
    }
}

// ---------------- fp32 -> fp16 hi/lo split (lo scaled by 2^11) ----------------
__global__ void split4(const float* __restrict__ x, __half* __restrict__ xh,
                       __half* __restrict__ xl) {
    int i4 = blockIdx.x * 256 + threadIdx.x;
    float4 v = ((const float4*)x)[i4];
    __half h0 = __float2half_rn(v.x), h1 = __float2half_rn(v.y);
    __half h2 = __float2half_rn(v.z), h3 = __float2half_rn(v.w);
    __half l0 = __float2half_rn((v.x - __half2float(h0)) * LOSCALE);
    __half l1 = __float2half_rn((v.y - __half2float(h1)) * LOSCALE);
    __half l2 = __float2half_rn((v.z - __half2float(h2)) * LOSCALE);
    __half l3 = __float2half_rn((v.w - __half2float(h3)) * LOSCALE);
    __half2* hp = (__half2*)(xh + (size_t)i4 * 4);
    __half2* lp = (__half2*)(xl + (size_t)i4 * 4);
    hp[0] = __halves2half2(h0, h1); hp[1] = __halves2half2(h2, h3);
    lp[0] = __halves2half2(l0, l1); lp[1] = __halves2half2(l2, l3);
}

// ---------------- weight transpose: W[K,N] -> Wh [N,K] fp16 (hi only) ----------------
__global__ void tsplit1(const float* __restrict__ W, __half* __restrict__ Wh, int K, int N) {
    __shared__ float tile[32][33];
    int n0 = blockIdx.x * 32, k0 = blockIdx.y * 32;
    int tx = threadIdx.x & 31, ty = threadIdx.x >> 5;   // 32x8
#pragma unroll
    for (int i = 0; i < 4; i++) {
        int k = k0 + ty + i * 8;
        tile[ty + i * 8][tx] = W[(size_t)k * N + n0 + tx];
    }
    __syncthreads();
#pragma unroll
    for (int i = 0; i < 4; i++) {
        int n = n0 + ty + i * 8;
        Wh[(size_t)n * K + k0 + tx] = __float2half_rn(tile[tx][ty + i * 8]);
    }
}

// ---------------- causal depthwise conv (K=4) + SiLU ----------------
__global__ void conv_silu_k(const float* __restrict__ x, const float* __restrict__ w,
                            float* __restrict__ y, int D) {
    int idx = blockIdx.x * 256 + threadIdx.x;
    int d = idx % D;
    int t = (idx / D) & (T_ - 1);
    float4 wv = *(const float4*)(w + d * 4);
    float acc = x[idx] * wv.w;
    if (t >= 1) acc += x[idx - D] * wv.z;
    if (t >= 2) acc += x[idx - 2 * D] * wv.y;
    if (t >= 3) acc += x[idx - 3 * D] * wv.x;
    y[idx] = acc / (1.f + expf(-acc));
}

// ---------------- per-(b,t,h) L2 norm over 256, in place, times scale ----------------
__global__ void l2norm_k(float* __restrict__ x, float scale) {
    int gw = (blockIdx.x * 256 + threadIdx.x) >> 5;
    int lane = threadIdx.x & 31;
    float* row = x + (size_t)gw * DKH;
    float4 v0 = *(const float4*)(row + lane * 8);
    float4 v1 = *(const float4*)(row + lane * 8 + 4);
    float ss = v0.x * v0.x + v0.y * v0.y + v0.z * v0.z + v0.w * v0.w +
               v1.x * v1.x + v1.y * v1.y + v1.z * v1.z + v1.w * v1.w;
#pragma unroll
    for (int o = 16; o; o >>= 1) ss += __shfl_xor_sync(0xffffffffu, ss, o);
    float r = rsqrtf(ss) * scale;
    v0.x *= r; v0.y *= r; v0.z *= r; v0.w *= r;
    v1.x *= r; v1.y *= r; v1.z *= r; v1.w *= r;
    *(float4*)(row + lane * 8) = v0;
    *(float4*)(row + lane * 8 + 4) = v1;
}

// ---------------- transpose Wa/Wb (2048x6 -> 6x2048) ----------------
__global__ void transpose6(const float* __restrict__ Wa, const float* __restrict__ Wb,
                           float* __restrict__ WaT, float* __restrict__ WbT) {
    int i = blockIdx.x * 256 + threadIdx.x;
    int c = i / H_, h = i % H_;
    WaT[h * HID_ + c] = Wa[i];
    WbT[h * HID_ + c] = Wb[i];
}

// ---------------- beta / decay projection ----------------
__global__ void proj_ab(const float* __restrict__ hid, const float* __restrict__ WaT,
                        const float* __restrict__ WbT, const float* __restrict__ A_log,
                        const float* __restrict__ dt_bias,
                        float* __restrict__ gdec, float* __restrict__ beta) {
    int gw = (blockIdx.x * 256 + threadIdx.x) >> 5;
    int lane = threadIdx.x & 31;
    const float* hr = hid + (size_t)gw * HID_;
    float da0 = 0, da1 = 0, da2 = 0, da3 = 0, da4 = 0, da5 = 0;
    float db0 = 0, db1 = 0, db2 = 0, db3 = 0, db4 = 0, db5 = 0;
    for (int c = lane; c < HID_; c += 32) {
        float hv = hr[c];
        da0 += hv * WaT[0 * HID_ + c]; db0 += hv * WbT[0 * HID_ + c];
        da1 += hv * WaT[1 * HID_ + c]; db1 += hv * WbT[1 * HID_ + c];
        da2 += hv * WaT[2 * HID_ + c]; db2 += hv * WbT[2 * HID_ + c];
        da3 += hv * WaT[3 * HID_ + c]; db3 += hv * WbT[3 * HID_ + c];
        da4 += hv * WaT[4 * HID_ + c]; db4 += hv * WbT[4 * HID_ + c];
        da5 += hv * WaT[5 * HID_ + c]; db5 += hv * WbT[5 * HID_ + c];
    }
#pragma unroll
    for (int o = 16; o; o >>= 1) {
        da0 += __shfl_xor_sync(~0u, da0, o); db0 += __shfl_xor_sync(~0u, db0, o);
        da1 += __shfl_xor_sync(~0u, da1, o); db1 += __shfl_xor_sync(~0u, db1, o);
        da2 += __shfl_xor_sync(~0u, da2, o); db2 += __shfl_xor_sync(~0u, db2, o);
        da3 += __shfl_xor_sync(~0u, da3, o); db3 += __shfl_xor_sync(~0u, db3, o);
        da4 += __shfl_xor_sync(~0u, da4, o); db4 += __shfl_xor_sync(~0u, db4, o);
        da5 += __shfl_xor_sync(~0u, da5, o); db5 += __shfl_xor_sync(~0u, db5, o);
    }
    if (lane == 0) {
        float da[6] = {da0, da1, da2, da3, da4, da5};
        float db[6] = {db0, db1, db2, db3, db4, db5};
#pragma unroll
        for (int h = 0; h < 6; h++) {
            float x = da[h] + dt_bias[h];
            float sp = (x > 20.f) ? x : log1pf(expf(x));
            gdec[gw * H_ + h] = -expf(A_log[h]) * sp;
            beta[gw * H_ + h] = 1.f / (1.f + expf(-db[h]));
        }
    }
}

// ---------------- RMSNorm * weight * silu(gate) -> fp16 hi/lo split ----------------
__global__ void norm_gate(const float* __restrict__ o, const float* __restrict__ gate,
                          const float* __restrict__ nw,
                          __half* __restrict__ yh, __half* __restrict__ yl) {
    int gw = (blockIdx.x * 256 + threadIdx.x) >> 5;
    int lane = threadIdx.x & 31;
    size_t base = (size_t)gw * DVH;
    float4 v[4];
    float ss = 0.f;
#pragma unroll
    for (int i = 0; i < 4; i++) {
        v[i] = *(const float4*)(o + base + (lane + i * 32) * 4);
        ss += v[i].x * v[i].x + v[i].y * v[i].y + v[i].z * v[i].z + v[i].w * v[i].w;
    }
#pragma unroll
    for (int off = 16; off; off >>= 1) ss += __shfl_xor_sync(0xffffffffu, ss, off);
    float r = rsqrtf(ss * (1.f / 512.f) + 1e-5f);
#pragma unroll
    for (int i = 0; i < 4; i++) {
        int d4 = (lane + i * 32) * 4;
        float4 gt = *(const float4*)(gate + base + d4);
        float4 w = *(const float4*)(nw + d4);
        float o0 = v[i].x * r * w.x * (gt.x / (1.f + expf(-gt.x)));
        float o1 = v[i].y * r * w.y * (gt.y / (1.f + expf(-gt.y)));
        float o2 = v[i].z * r * w.z * (gt.z / (1.f + expf(-gt.z)));
        float o3 = v[i].w * r * w.w * (gt.w / (1.f + expf(-gt.w)));
        __half h0 = __float2half_rn(o0), h1 = __float2half_rn(o1);
        __half h2 = __float2half_rn(o2), h3 = __float2half_rn(o3);
        __half2* hp = (__half2*)(yh + base + d4);
        __half2* lp = (__half2*)(yl + base + d4);
        hp[0] = __halves2half2(h0, h1);
        hp[1] = __halves2half2(h2, h3);
        lp[0] = __halves2half2(__float2half_rn((o0 - __half2float(h0)) * LOSCALE),
                               __float2half_rn((o1 - __half2float(h1)) * LOSCALE));
        lp[1] = __halves2half2(__float2half_rn((o2 - __half2float(h2)) * LOSCALE),
                               __float2half_rn((o3 - __half2float(h3)) * LOSCALE));
    }
}

// ---------------- launch ----------------
extern "C" void kernel_launch(void* const* d_in, const int* in_sizes, int n_in,
                              void* d_out, int out_size) {
    const float* hid  = (const float*)d_in[0];
    const float* Wq   = (const float*)d_in[1];
    const float* Wk   = (const float*)d_in[2];
    const float* Wv   = (const float*)d_in[3];
    const float* Wa   = (const float*)d_in[4];
    const float* Wb   = (const float*)d_in[5];
    const float* Wg   = (const float*)d_in[6];
    const float* Wo   = (const float*)d_in[7];
    const float* cwq  = (const float*)d_in[8];
    const float* cwk  = (const float*)d_in[9];
    const float* cwv  = (const float*)d_in[10];
    const float* Alog = (const float*)d_in[11];
    const float* dtb  = (const float*)d_in[12];
    const float* nw   = (const float*)d_in[13];

    float *xq, *xk, *xv, *gt, *qn, *kn, *vn, *od, *gd, *bt, *wat, *wbt;
    __half *ah, *al, *yh, *yl, *wqkvh, *wgh, *woh;
    cudaGetSymbolAddress((void**)&xq, g_xq);
    cudaGetSymbolAddress((void**)&xk, g_xk);
    cudaGetSymbolAddress((void**)&xv, g_xv);
    cudaGetSymbolAddress((void**)&gt, g_gt);
    cudaGetSymbolAddress((void**)&qn, g_qn);
    cudaGetSymbolAddress((void**)&kn, g_kn);
    cudaGetSymbolAddress((void**)&vn, g_vn);
    cudaGetSymbolAddress((void**)&od, g_od);
    cudaGetSymbolAddress((void**)&gd, g_gd);
    cudaGetSymbolAddress((void**)&bt, g_bt);
    cudaGetSymbolAddress((void**)&wat, g_wat);
    cudaGetSymbolAddress((void**)&wbt, g_wbt);
    cudaGetSymbolAddress((void**)&ah, g_ah);
    cudaGetSymbolAddress((void**)&al, g_al);
    cudaGetSymbolAddress((void**)&yh, g_yh);
    cudaGetSymbolAddress((void**)&yl, g_yl);
    cudaGetSymbolAddress((void**)&wqkvh, g_wqkvh);
    cudaGetSymbolAddress((void**)&wgh, g_wgh);
    cudaGetSymbolAddress((void**)&woh, g_woh);

    cudaFuncSetAttribute(gemm_hx2, cudaFuncAttributeMaxDynamicSharedMemorySize, GEMM_SMEM);
    cudaFuncSetAttribute(scan_gemm, cudaFuncAttributeMaxDynamicSharedMemorySize, GEMM_SMEM);

    // fp16 prep: activations (hi+lo) + weights (hi only, transposed to [N,K])
    split4<<<(ROWS_ * HID_ / 4) / 256, 256>>>(hid, ah, al);
    tsplit1<<<dim3(KEYD / 32, HID_ / 32), 256>>>(Wq, wqkvh, HID_, KEYD);
    tsplit1<<<dim3(KEYD / 32, HID_ / 32), 256>>>(Wk, wqkvh + (size_t)KEYD * HID_, HID_, KEYD);
    tsplit1<<<dim3(VALD / 32, HID_ / 32), 256>>>(Wv, wqkvh + (size_t)2 * KEYD * HID_, HID_, VALD);
    tsplit1<<<dim3(VALD / 32, HID_ / 32), 256>>>(Wg, wgh, HID_, VALD);
    tsplit1<<<dim3(HID_ / 32, VALD / 32), 256>>>(Wo, woh, VALD, HID_);

    // beta / decay (before the fat kernel)
    transpose6<<<(H_ * HID_) / 256, 256>>>(Wa, Wb, wat, wbt);
    proj_ab<<<(ROWS_ * 32) / 256, 256>>>(hid, wat, wbt, Alog, dtb, gd, bt);

    // fused Q|K|V projection (N = 6144, 3-way routed epilogue)
    gemm_hx2<<<dim3((2 * KEYD + VALD) / 128, ROWS_ / 128), 256, GEMM_SMEM>>>(
        ah, al, wqkvh, xq, xk, xv, KEYD, 2 * KEYD, KEYD, KEYD, VALD, HID_);

    // conv + silu
    conv_silu_k<<<(ROWS_ * KEYD) / 256, 256>>>(xq, cwq, qn, KEYD);
    conv_silu_k<<<(ROWS_ * KEYD) / 256, 256>>>(xk, cwk, kn, KEYD);
    conv_silu_k<<<(ROWS_ * VALD) / 256, 256>>>(xv, cwv, vn, VALD);

    // l2 norms (q also scaled by dk^-0.5 = 1/16)
    l2norm_k<<<(ROWS_ * H_ * 32) / 256, 256>>>(qn, 0.0625f);
    l2norm_k<<<(ROWS_ * H_ * 32) / 256, 256>>>(kn, 1.0f);

    // fat kernel: scan on 96 CTAs + gate GEMM (Wg) backfilling idle SMs
    scan_gemm<<<SCAN_CTAS + (VALD / 128) * (ROWS_ / 128), 256, GEMM_SMEM>>>(
        qn, kn, vn, gd, bt, od, ah, al, wgh, gt);

    // rmsnorm * weight * silu(gate) -> fp16 hi/lo
    norm_gate<<<(ROWS_ * H_ * 32) / 256, 256>>>(od, gt, nw, yh, yl);

    // output projection -> d_out
    gemm_hx2<<<dim3(HID_ / 128, ROWS_ / 128), 256, GEMM_SMEM>>>(
        yh, yl, woh, (float*)d_out, (float*)d_out, (float*)d_out,
        HID_, HID_, HID_, HID_, HID_, VALD);
}